// round 6
// baseline (speedup 1.0000x reference)
#include <cuda_runtime.h>
#include <cuda_bf16.h>
#include <cstdint>

// ---------------- problem constants ----------------
#define T_    256
#define B_    128
#define E_    1024
#define H_    1024
#define N4_   4096
#define BH_   (B_ * H_)
#define NSPLIT 4            // K-splits for the per-step h-GEMM

// ---------------- static device scratch ----------------
// NOTE: weights and z use GATE-INTERLEAVED column order: col' = 4*unit + gate
__device__ float          g_zx[(size_t)T_ * B_ * N4_];   // x-part preactivations (interleaved)
__device__ float          g_zh[NSPLIT * B_ * N4_];       // per-step h-part partials (interleaved)
__device__ float          g_c[BH_];                      // cell state
__device__ float4         g_b4[H_];                      // interleaved bias {bg,bi,bf,bo}[u]
__device__ __nv_bfloat16  g_eh[(size_t)T_ * B_ * E_];    // embeds hi
__device__ __nv_bfloat16  g_el[(size_t)T_ * B_ * E_];    // embeds lo
__device__ __nv_bfloat16  g_wxh[N4_ * 1024];             // Wx hi (interleaved rows, K-major)
__device__ __nv_bfloat16  g_wxl[N4_ * 1024];
__device__ __nv_bfloat16  g_whh[N4_ * 1024];             // Wh hi (interleaved rows)
__device__ __nv_bfloat16  g_whl[N4_ * 1024];
__device__ __nv_bfloat16  g_hhi[BH_];                    // h_{t-1} hi
__device__ __nv_bfloat16  g_hlo[BH_];                    // h_{t-1} lo
__device__ unsigned       g_barrier_cnt;                 // grid barrier (monotonic)
__device__ unsigned       g_pcnt[32];                    // per-nt partial counters (monotonic)

// ---------------- arch-generic PTX helpers ----------------
__device__ __forceinline__ uint32_t smem_u32(const void* p) {
    uint32_t a;
    asm("{ .reg .u64 t; cvta.to.shared.u64 t, %1; cvt.u32.u64 %0, t; }" : "=r"(a) : "l"(p));
    return a;
}
__device__ __forceinline__ void ldsm4(uint32_t r[4], uint32_t saddr) {
    asm volatile("ldmatrix.sync.aligned.m8n8.x4.shared.b16 {%0,%1,%2,%3}, [%4];"
                 : "=r"(r[0]), "=r"(r[1]), "=r"(r[2]), "=r"(r[3]) : "r"(saddr));
}
__device__ __forceinline__ void mma16816(float c[4], const uint32_t a[4],
                                         uint32_t b0, uint32_t b1) {
    asm volatile("mma.sync.aligned.m16n8k16.row.col.f32.bf16.bf16.f32 "
                 "{%0,%1,%2,%3}, {%4,%5,%6,%7}, {%8,%9}, {%0,%1,%2,%3};"
                 : "+f"(c[0]), "+f"(c[1]), "+f"(c[2]), "+f"(c[3])
                 : "r"(a[0]), "r"(a[1]), "r"(a[2]), "r"(a[3]), "r"(b0), "r"(b1));
}
#define CP_ASYNC16(dst, src) \
    asm volatile("cp.async.cg.shared.global [%0], [%1], 16;" :: "r"(dst), "l"(src))
#define CP_COMMIT() asm volatile("cp.async.commit_group;" ::: "memory")
#define CP_WAIT1()  asm volatile("cp.async.wait_group 1;" ::: "memory")
#define CP_WAIT0()  asm volatile("cp.async.wait_group 0;" ::: "memory")

// ---------------- grid barrier (all 128 CTAs co-resident) ----------------
__device__ __forceinline__ void grid_barrier(unsigned target) {
    __syncthreads();
    if (threadIdx.x == 0) {
        __threadfence();
        atomicAdd(&g_barrier_cnt, 1u);
        while (*(volatile unsigned*)&g_barrier_cnt < target) { }
        __threadfence();
    }
    __syncthreads();
}

// ---------------- batch 3-plane bf16 GEMM (known-good) ----------------
__global__ __launch_bounds__(256, 1)
void gemm_mma(const __nv_bfloat16* __restrict__ Ah, const __nv_bfloat16* __restrict__ Al,
              int lda,
              const __nv_bfloat16* __restrict__ Bh, const __nv_bfloat16* __restrict__ Bl,
              float* __restrict__ C, size_t csplit_stride, int klen)
{
    extern __shared__ __align__(128) char sm[];

    const int tid  = threadIdx.x;
    const int lane = tid & 31;
    const int wid  = tid >> 5;
    const int wm   = wid & 1;
    const int wn   = wid >> 1;
    const int nt = blockIdx.x, mt = blockIdx.y, kz = blockIdx.z;
    const int kofs = kz * klen;
    const int nstages = klen >> 6;

    const __nv_bfloat16* a_h = Ah + (size_t)mt * 128 * lda + kofs;
    const __nv_bfloat16* a_l = Al + (size_t)mt * 128 * lda + kofs;
    const __nv_bfloat16* b_h = Bh + (size_t)nt * 128 * 1024 + kofs;
    const __nv_bfloat16* b_l = Bl + (size_t)nt * 128 * 1024 + kofs;

    const int lrow = tid >> 3;
    const int lc   = tid & 7;

#define LOAD_STAGE(buf, s) do {                                                    \
        char* dst_ = sm + (buf) * 65536;                                           \
        const __nv_bfloat16* s0_ = a_h + (s) * 64;                                 \
        const __nv_bfloat16* s1_ = a_l + (s) * 64;                                 \
        const __nv_bfloat16* s2_ = b_h + (s) * 64;                                 \
        const __nv_bfloat16* s3_ = b_l + (s) * 64;                                 \
        _Pragma("unroll")                                                          \
        for (int p = 0; p < 4; ++p) {                                              \
            int row = lrow + p * 32;                                               \
            uint32_t so = row * 128 + ((lc ^ (row & 7)) << 4);                     \
            CP_ASYNC16(smem_u32(dst_ + 0     + so), s0_ + (size_t)row * lda + lc * 8); \
            CP_ASYNC16(smem_u32(dst_ + 16384 + so), s1_ + (size_t)row * lda + lc * 8); \
            CP_ASYNC16(smem_u32(dst_ + 32768 + so), s2_ + (size_t)row * 1024 + lc * 8); \
            CP_ASYNC16(smem_u32(dst_ + 49152 + so), s3_ + (size_t)row * 1024 + lc * 8); \
        }                                                                          \
        CP_COMMIT();                                                               \
    } while (0)

    float cacc[4][4][4];
#pragma unroll
    for (int mi = 0; mi < 4; ++mi)
#pragma unroll
        for (int ni = 0; ni < 4; ++ni)
#pragma unroll
            for (int q = 0; q < 4; ++q) cacc[mi][ni][q] = 0.0f;

    LOAD_STAGE(0, 0);
    if (nstages > 1) LOAD_STAGE(1, 1);

#pragma unroll 1
    for (int s = 0; s < nstages; ++s) {
        if (s + 1 < nstages) { CP_WAIT1(); } else { CP_WAIT0(); }
        __syncthreads();

        const char* base = sm + (s & 1) * 65536;
#pragma unroll
        for (int j = 0; j < 4; ++j) {
            uint32_t aH[4][4], aL[4][4], bH[2][4], bL[2][4];
#pragma unroll
            for (int mi = 0; mi < 4; ++mi) {
                int row = wm * 64 + mi * 16 + (lane & 15);
                int ch  = 2 * j + (lane >> 4);
                uint32_t off = row * 128 + ((ch ^ (row & 7)) << 4);
                ldsm4(aH[mi], smem_u32(base + 0     + off));
                ldsm4(aL[mi], smem_u32(base + 16384 + off));
            }
#pragma unroll
            for (int pi = 0; pi < 2; ++pi) {
                int row = wn * 32 + pi * 16 + (lane & 7) + ((lane & 16) >> 1);
                int ch  = 2 * j + ((lane >> 3) & 1);
                uint32_t off = row * 128 + ((ch ^ (row & 7)) << 4);
                ldsm4(bH[pi], smem_u32(base + 32768 + off));
                ldsm4(bL[pi], smem_u32(base + 49152 + off));
            }
#pragma unroll
            for (int mi = 0; mi < 4; ++mi)
#pragma unroll
                for (int ni = 0; ni < 4; ++ni) {
                    uint32_t bh0 = bH[ni >> 1][(ni & 1) * 2];
                    uint32_t bh1 = bH[ni >> 1][(ni & 1) * 2 + 1];
                    uint32_t bl0 = bL[ni >> 1][(ni & 1) * 2];
                    uint32_t bl1 = bL[ni >> 1][(ni & 1) * 2 + 1];
                    mma16816(cacc[mi][ni], aH[mi], bh0, bh1);
                    mma16816(cacc[mi][ni], aH[mi], bl0, bl1);
                    mma16816(cacc[mi][ni], aL[mi], bh0, bh1);
                }
        }
        __syncthreads();
        if (s + 2 < nstages) LOAD_STAGE(s & 1, s + 2);
    }

    float* cb = C + (size_t)kz * csplit_stride + (size_t)mt * 128 * N4_ + nt * 128;
#pragma unroll
    for (int mi = 0; mi < 4; ++mi)
#pragma unroll
        for (int ni = 0; ni < 4; ++ni) {
            int r   = wm * 64 + mi * 16 + (lane >> 2);
            int col = wn * 32 + ni * 8 + (lane & 3) * 2;
            *(float2*)(cb + (size_t)r * N4_ + col) =
                make_float2(cacc[mi][ni][0], cacc[mi][ni][1]);
            *(float2*)(cb + (size_t)(r + 8) * N4_ + col) =
                make_float2(cacc[mi][ni][2], cacc[mi][ni][3]);
        }
#undef LOAD_STAGE
}

// ---------------- persistent recurrence kernel ----------------
// 128 CTAs (1/SM). CTA = (nt 0..31, kz 0..3). kz==0 CTA is the "owner" of its
// 128 interleaved columns = 32 units; it performs the gate eltwise locally.
// smem: [0,64K) Wh-hi sub-slabs, [64K,128K) Wh-lo, [128K,192K) h double buffer.
#define PK_CTAS  128
#define PK_SMEM  196608
#define SM_WHI(s)    (sm + (s) * 16384)
#define SM_WLO(s)    (sm + 65536 + (s) * 16384)
#define SM_HBUF(b)   (sm + 131072 + (b) * 32768)

__global__ __launch_bounds__(256, 1)
void lstm_persistent(float* __restrict__ out)
{
    extern __shared__ __align__(128) char sm[];

    const int tid  = threadIdx.x;
    const int lane = tid & 31;
    const int wid  = tid >> 5;
    const int wm   = wid & 1;
    const int wn   = wid >> 1;
    const int cta  = blockIdx.x;
    const int nt   = cta & 31;
    const int kz   = cta >> 5;

    const int lrow = tid >> 3;
    const int lc   = tid & 7;

    // ---- resident W slab (hi+lo, 4 K64 sub-slabs) ----
#pragma unroll
    for (int sub = 0; sub < 4; ++sub) {
#pragma unroll
        for (int p = 0; p < 4; ++p) {
            int row = lrow + p * 32;
            uint32_t so = row * 128 + ((lc ^ (row & 7)) << 4);
            size_t gofs = (size_t)(nt * 128 + row) * 1024 + kz * 256 + sub * 64 + lc * 8;
            CP_ASYNC16(smem_u32(SM_WHI(sub) + so), g_whh + gofs);
            CP_ASYNC16(smem_u32(SM_WLO(sub) + so), g_whl + gofs);
        }
    }
    CP_COMMIT();

#define LOADH(buf, s) do {                                                          \
        char* dst_ = SM_HBUF(buf);                                                  \
        _Pragma("unroll")                                                           \
        for (int p = 0; p < 4; ++p) {                                               \
            int row = lrow + p * 32;                                                \
            uint32_t so = row * 128 + ((lc ^ (row & 7)) << 4);                      \
            size_t go = (size_t)row * 1024 + kz * 256 + (s) * 64 + lc * 8;          \
            CP_ASYNC16(smem_u32(dst_ + so),         g_hhi + go);                    \
            CP_ASYNC16(smem_u32(dst_ + 16384 + so), g_hlo + go);                    \
        }                                                                           \
        CP_COMMIT();                                                                \
    } while (0)

#pragma unroll 1
    for (int t = 1; t < T_; ++t) {
        // ONE global barrier per step: h_{t-1} visible to all CTAs
        grid_barrier((unsigned)t * PK_CTAS);

        LOADH(0, 0);
        LOADH(1, 1);

        float cacc[4][4][4];
#pragma unroll
        for (int mi = 0; mi < 4; ++mi)
#pragma unroll
            for (int ni = 0; ni < 4; ++ni)
#pragma unroll
                for (int q = 0; q < 4; ++q) cacc[mi][ni][q] = 0.0f;

#pragma unroll 1
        for (int s = 0; s < 4; ++s) {
            if (s + 1 < 4) { CP_WAIT1(); } else { CP_WAIT0(); }
            __syncthreads();

            const char* abase  = SM_HBUF(s & 1);
            const char* bhbase = SM_WHI(s);
            const char* blbase = SM_WLO(s);
#pragma unroll
            for (int j = 0; j < 4; ++j) {
                uint32_t aH[4][4], aL[4][4], bH[2][4], bL[2][4];
#pragma unroll
                for (int mi = 0; mi < 4; ++mi) {
                    int row = wm * 64 + mi * 16 + (lane & 15);
                    int ch  = 2 * j + (lane >> 4);
                    uint32_t off = row * 128 + ((ch ^ (row & 7)) << 4);
                    ldsm4(aH[mi], smem_u32(abase + off));
                    ldsm4(aL[mi], smem_u32(abase + 16384 + off));
                }
#pragma unroll
                for (int pi = 0; pi < 2; ++pi) {
                    int row = wn * 32 + pi * 16 + (lane & 7) + ((lane & 16) >> 1);
                    int ch  = 2 * j + ((lane >> 3) & 1);
                    uint32_t off = row * 128 + ((ch ^ (row & 7)) << 4);
                    ldsm4(bH[pi], smem_u32(bhbase + off));
                    ldsm4(bL[pi], smem_u32(blbase + off));
                }
#pragma unroll
                for (int mi = 0; mi < 4; ++mi)
#pragma unroll
                    for (int ni = 0; ni < 4; ++ni) {
                        uint32_t bh0 = bH[ni >> 1][(ni & 1) * 2];
                        uint32_t bh1 = bH[ni >> 1][(ni & 1) * 2 + 1];
                        uint32_t bl0 = bL[ni >> 1][(ni & 1) * 2];
                        uint32_t bl1 = bL[ni >> 1][(ni & 1) * 2 + 1];
                        mma16816(cacc[mi][ni], aH[mi], bh0, bh1);
                        mma16816(cacc[mi][ni], aH[mi], bl0, bl1);
                        mma16816(cacc[mi][ni], aL[mi], bh0, bh1);
                    }
            }
            __syncthreads();
            if (s + 2 < 4) LOADH(s & 1, s + 2);
        }

        // write z partials for this (nt, kz)
        {
            float* cb = g_zh + (size_t)kz * (B_ * N4_) + nt * 128;
#pragma unroll
            for (int mi = 0; mi < 4; ++mi)
#pragma unroll
                for (int ni = 0; ni < 4; ++ni) {
                    int r   = wm * 64 + mi * 16 + (lane >> 2);
                    int col = wn * 32 + ni * 8 + (lane & 3) * 2;
                    *(float2*)(cb + (size_t)r * N4_ + col) =
                        make_float2(cacc[mi][ni][0], cacc[mi][ni][1]);
                    *(float2*)(cb + (size_t)(r + 8) * N4_ + col) =
                        make_float2(cacc[mi][ni][2], cacc[mi][ni][3]);
                }
        }
        __syncthreads();                       // all partial stores issued
        if (kz != 0) {
            if (tid == 0) {
                __threadfence();               // release
                atomicAdd(&g_pcnt[nt], 1u);
            }
            continue;                          // partner done; next step's barrier
        }

        // ---- owner (kz==0): wait partners, gather, gate eltwise ----
        if (tid == 0) {
            __threadfence();                   // own partial visible
            unsigned tgt = 3u * (unsigned)t;
            while (*(volatile unsigned*)&g_pcnt[nt] < tgt) { }
            __threadfence();                   // acquire
        }
        __syncthreads();

        {
            const float* zxrow = g_zx + (size_t)t * B_ * N4_;
#pragma unroll 1
            for (int it = 0; it < 4; ++it) {
                int e  = tid + it * 256;       // 0..1023
                int b  = e >> 3;
                int uq = e & 7;
                size_t rowoff = (size_t)b * N4_ + nt * 128 + uq * 16;

                const float4* px = (const float4*)(zxrow + rowoff);
                float4 z0 = __ldg(px + 0), z1 = __ldg(px + 1),
                       z2 = __ldg(px + 2), z3 = __ldg(px + 3);
#pragma unroll
                for (int kzi = 0; kzi < 4; ++kzi) {
                    const float4* pp =
                        (const float4*)(g_zh + (size_t)kzi * (B_ * N4_) + rowoff);
                    float4 a0 = __ldcg(pp + 0), a1 = __ldcg(pp + 1),
                           a2 = __ldcg(pp + 2), a3 = __ldcg(pp + 3);
                    z0.x += a0.x; z0.y += a0.y; z0.z += a0.z; z0.w += a0.w;
                    z1.x += a1.x; z1.y += a1.y; z1.z += a1.z; z1.w += a1.w;
                    z2.x += a2.x; z2.y += a2.y; z2.z += a2.z; z2.w += a2.w;
                    z3.x += a3.x; z3.y += a3.y; z3.z += a3.z; z3.w += a3.w;
                }
                float4 zz[4] = {z0, z1, z2, z3};

                int u0 = nt * 32 + uq * 4;
                float4 c4 = *(float4*)(g_c + (size_t)b * 1024 + u0);
                float cc[4] = {c4.x, c4.y, c4.z, c4.w};
                float hv[4], cv[4];
#pragma unroll
                for (int j = 0; j < 4; ++j) {
                    float4 bb = g_b4[u0 + j];
                    float zg = zz[j].x + bb.x;
                    float zi = zz[j].y + bb.y;
                    float zf = zz[j].z + bb.z;
                    float zo = zz[j].w + bb.w;
                    float g  = tanhf(zg);
                    float ii = 1.0f / (1.0f + expf(-zi));
                    float f  = 1.0f / (1.0f + expf(-zf));
                    float o  = 1.0f / (1.0f + expf(-zo));
                    float c  = f * cc[j] + ii * g;
                    cv[j] = c;
                    hv[j] = o * tanhf(c);
                }
                *(float4*)(g_c + (size_t)b * 1024 + u0) =
                    make_float4(cv[0], cv[1], cv[2], cv[3]);
                *(float4*)(out + ((size_t)t * B_ + b) * 1024 + u0) =
                    make_float4(hv[0], hv[1], hv[2], hv[3]);

                union { __nv_bfloat16 v[4]; uint2 u; } hh, hl;
#pragma unroll
                for (int j = 0; j < 4; ++j) {
                    __nv_bfloat16 h = __float2bfloat16(hv[j]);
                    hh.v[j] = h;
                    hl.v[j] = __float2bfloat16(hv[j] - __bfloat162float(h));
                }
                *(uint2*)(g_hhi + (size_t)b * 1024 + u0) = hh.u;
                *(uint2*)(g_hlo + (size_t)b * 1024 + u0) = hl.u;
            }
        }
        // owner's h stores are made visible by the fence inside next grid_barrier
    }
#undef LOADH
}

// ---------------- prep kernels ----------------
__global__ void split_plane(const float* __restrict__ src, __nv_bfloat16* __restrict__ hi,
                            __nv_bfloat16* __restrict__ lo, int n) {
    int i = blockIdx.x * blockDim.x + threadIdx.x;
    if (i < n) {
        float v = src[i];
        __nv_bfloat16 h = __float2bfloat16(v);
        hi[i] = h;
        lo[i] = __float2bfloat16(v - __bfloat162float(h));
    }
}

// gate-INTERLEAVED weight split: dest row = 4*unit + gate
__global__ void split_W(const float* __restrict__ Wg, const float* __restrict__ Wi,
                        const float* __restrict__ Wf, const float* __restrict__ Wo) {
    int idx = blockIdx.x * blockDim.x + threadIdx.x;
    if (idx >= 4 * 1024 * 2048) return;
    int gate = idx >> 21;
    int rem  = idx & ((1 << 21) - 1);
    int n    = rem >> 11;
    int k    = rem & 2047;
    const float* W = (gate == 0) ? Wg : (gate == 1) ? Wi : (gate == 2) ? Wf : Wo;
    float v = W[(size_t)n * 2048 + k];
    __nv_bfloat16 h = __float2bfloat16(v);
    __nv_bfloat16 l = __float2bfloat16(v - __bfloat162float(h));
    int gr = 4 * n + gate;                  // interleaved row
    if (k < 1024) {
        g_wxh[(size_t)gr * 1024 + k] = h;
        g_wxl[(size_t)gr * 1024 + k] = l;
    } else {
        g_whh[(size_t)gr * 1024 + (k - 1024)] = h;
        g_whl[(size_t)gr * 1024 + (k - 1024)] = l;
    }
}

__global__ void init_state(float* __restrict__ out,
                           const float* __restrict__ bg, const float* __restrict__ bi,
                           const float* __restrict__ bf, const float* __restrict__ bo) {
    int i = blockIdx.x * blockDim.x + threadIdx.x;
    if (i < BH_) {
        out[i] = 0.0f;
        g_c[i] = 0.0f;
        g_hhi[i] = __float2bfloat16(0.0f);
        g_hlo[i] = __float2bfloat16(0.0f);
    }
    if (i < H_) g_b4[i] = make_float4(bg[i], bi[i], bf[i], bo[i]);
    if (i < 32) g_pcnt[i] = 0;
    if (i == 0) g_barrier_cnt = 0;
}

// ---------------- launch ----------------
#define GEMM_SMEM (2 * 65536)

extern "C" void kernel_launch(void* const* d_in, const int* in_sizes, int n_in,
                              void* d_out, int out_size)
{
    const float* embeds = (const float*)d_in[0];
    const float* Wg = (const float*)d_in[1];
    const float* Wi = (const float*)d_in[2];
    const float* Wf = (const float*)d_in[3];
    const float* Wo = (const float*)d_in[4];
    const float* bg = (const float*)d_in[5];
    const float* bi = (const float*)d_in[6];
    const float* bf = (const float*)d_in[7];
    const float* bo = (const float*)d_in[8];
    float* out = (float*)d_out;

    cudaFuncSetAttribute(gemm_mma, cudaFuncAttributeMaxDynamicSharedMemorySize, GEMM_SMEM);
    cudaFuncSetAttribute(lstm_persistent, cudaFuncAttributeMaxDynamicSharedMemorySize, PK_SMEM);

    __nv_bfloat16 *p_eh, *p_el, *p_wxh, *p_wxl;
    float *p_zx;
    cudaGetSymbolAddress((void**)&p_eh,  g_eh);
    cudaGetSymbolAddress((void**)&p_el,  g_el);
    cudaGetSymbolAddress((void**)&p_wxh, g_wxh);
    cudaGetSymbolAddress((void**)&p_wxl, g_wxl);
    cudaGetSymbolAddress((void**)&p_zx,  g_zx);

    // prep
    {
        int n = T_ * B_ * E_;
        split_plane<<<(n + 255) / 256, 256>>>(embeds, p_eh, p_el, n);
    }
    split_W<<<(4 * 1024 * 2048 + 255) / 256, 256>>>(Wg, Wi, Wf, Wo);
    init_state<<<(BH_ + 255) / 256, 256>>>(out, bg, bi, bf, bo);

    // batch: Zx[t] = x_t @ Wx'^T for all t (M = 32768 rows, K = 1024), interleaved cols
    gemm_mma<<<dim3(32, 256, 1), 256, GEMM_SMEM>>>(p_eh, p_el, 1024, p_wxh, p_wxl,
                                                   p_zx, 0, 1024);

    // recurrence: one persistent kernel, all 255 steps
    lstm_persistent<<<PK_CTAS, 256, PK_SMEM>>>(out);
}

// round 7
// speedup vs baseline: 1.3583x; 1.3583x over previous
#include <cuda_runtime.h>
#include <cuda_bf16.h>
#include <cstdint>

// ---------------- problem constants ----------------
#define T_    256
#define B_    128
#define E_    1024
#define H_    1024
#define N4_   4096
#define BH_   (B_ * H_)

// ---------------- static device scratch ----------------
// weights / z use GATE-INTERLEAVED column order: col' = 4*unit + gate
__device__ float          g_zx[(size_t)T_ * B_ * N4_];   // x-part preactivations (interleaved)
__device__ float4         g_b4[H_];                      // interleaved bias {bg,bi,bf,bo}[u]
__device__ __nv_bfloat16  g_eh[(size_t)T_ * B_ * E_];    // embeds hi
__device__ __nv_bfloat16  g_el[(size_t)T_ * B_ * E_];    // embeds lo
__device__ __nv_bfloat16  g_wxh[N4_ * 1024];             // Wx hi (interleaved rows, K-major)
__device__ __nv_bfloat16  g_wxl[N4_ * 1024];
__device__ __nv_bfloat16  g_whh[N4_ * 1024];             // Wh hi (interleaved rows)
__device__ __nv_bfloat16  g_whl[N4_ * 1024];
__device__ __nv_bfloat16  g_hh[2][BH_];                  // h double buffer, hi plane
__device__ __nv_bfloat16  g_hl[2][BH_];                  // h double buffer, lo plane
__device__ unsigned       g_barrier_cnt;                 // grid barrier (monotonic)

// ---------------- arch-generic PTX helpers ----------------
__device__ __forceinline__ uint32_t smem_u32(const void* p) {
    uint32_t a;
    asm("{ .reg .u64 t; cvta.to.shared.u64 t, %1; cvt.u32.u64 %0, t; }" : "=r"(a) : "l"(p));
    return a;
}
__device__ __forceinline__ void ldsm4(uint32_t r[4], uint32_t saddr) {
    asm volatile("ldmatrix.sync.aligned.m8n8.x4.shared.b16 {%0,%1,%2,%3}, [%4];"
                 : "=r"(r[0]), "=r"(r[1]), "=r"(r[2]), "=r"(r[3]) : "r"(saddr));
}
__device__ __forceinline__ void mma16816(float c[4], const uint32_t a[4],
                                         uint32_t b0, uint32_t b1) {
    asm volatile("mma.sync.aligned.m16n8k16.row.col.f32.bf16.bf16.f32 "
                 "{%0,%1,%2,%3}, {%4,%5,%6,%7}, {%8,%9}, {%0,%1,%2,%3};"
                 : "+f"(c[0]), "+f"(c[1]), "+f"(c[2]), "+f"(c[3])
                 : "r"(a[0]), "r"(a[1]), "r"(a[2]), "r"(a[3]), "r"(b0), "r"(b1));
}
#define CP_ASYNC16(dst, src) \
    asm volatile("cp.async.cg.shared.global [%0], [%1], 16;" :: "r"(dst), "l"(src))
#define CP_COMMIT() asm volatile("cp.async.commit_group;" ::: "memory")
#define CP_WAIT0()  asm volatile("cp.async.wait_group 0;" ::: "memory")
#define CP_WAIT1()  asm volatile("cp.async.wait_group 1;" ::: "memory")
#define CP_WAIT2()  asm volatile("cp.async.wait_group 2;" ::: "memory")

// ---------------- grid barrier (all 128 CTAs co-resident) ----------------
__device__ __forceinline__ void grid_barrier(unsigned target) {
    __syncthreads();
    if (threadIdx.x == 0) {
        __threadfence();
        atomicAdd(&g_barrier_cnt, 1u);
        while (*(volatile unsigned*)&g_barrier_cnt < target) { }
        __threadfence();
    }
    __syncthreads();
}

// ---------------- batch 3-plane bf16 GEMM (known-good from R4-R6) ----------------
__global__ __launch_bounds__(256, 1)
void gemm_mma(const __nv_bfloat16* __restrict__ Ah, const __nv_bfloat16* __restrict__ Al,
              int lda,
              const __nv_bfloat16* __restrict__ Bh, const __nv_bfloat16* __restrict__ Bl,
              float* __restrict__ C, size_t csplit_stride, int klen)
{
    extern __shared__ __align__(128) char sm[];

    const int tid  = threadIdx.x;
    const int lane = tid & 31;
    const int wid  = tid >> 5;
    const int wm   = wid & 1;
    const int wn   = wid >> 1;
    const int nt = blockIdx.x, mt = blockIdx.y, kz = blockIdx.z;
    const int kofs = kz * klen;
    const int nstages = klen >> 6;

    const __nv_bfloat16* a_h = Ah + (size_t)mt * 128 * lda + kofs;
    const __nv_bfloat16* a_l = Al + (size_t)mt * 128 * lda + kofs;
    const __nv_bfloat16* b_h = Bh + (size_t)nt * 128 * 1024 + kofs;
    const __nv_bfloat16* b_l = Bl + (size_t)nt * 128 * 1024 + kofs;

    const int lrow = tid >> 3;
    const int lc   = tid & 7;

#define LOAD_STAGE(buf, s) do {                                                    \
        char* dst_ = sm + (buf) * 65536;                                           \
        const __nv_bfloat16* s0_ = a_h + (s) * 64;                                 \
        const __nv_bfloat16* s1_ = a_l + (s) * 64;                                 \
        const __nv_bfloat16* s2_ = b_h + (s) * 64;                                 \
        const __nv_bfloat16* s3_ = b_l + (s) * 64;                                 \
        _Pragma("unroll")                                                          \
        for (int p = 0; p < 4; ++p) {                                              \
            int row = lrow + p * 32;                                               \
            uint32_t so = row * 128 + ((lc ^ (row & 7)) << 4);                     \
            CP_ASYNC16(smem_u32(dst_ + 0     + so), s0_ + (size_t)row * lda + lc * 8); \
            CP_ASYNC16(smem_u32(dst_ + 16384 + so), s1_ + (size_t)row * lda + lc * 8); \
            CP_ASYNC16(smem_u32(dst_ + 32768 + so), s2_ + (size_t)row * 1024 + lc * 8); \
            CP_ASYNC16(smem_u32(dst_ + 49152 + so), s3_ + (size_t)row * 1024 + lc * 8); \
        }                                                                          \
        CP_COMMIT();                                                               \
    } while (0)

    float cacc[4][4][4];
#pragma unroll
    for (int mi = 0; mi < 4; ++mi)
#pragma unroll
        for (int ni = 0; ni < 4; ++ni)
#pragma unroll
            for (int q = 0; q < 4; ++q) cacc[mi][ni][q] = 0.0f;

    LOAD_STAGE(0, 0);
    if (nstages > 1) LOAD_STAGE(1, 1);

#pragma unroll 1
    for (int s = 0; s < nstages; ++s) {
        if (s + 1 < nstages) { CP_WAIT1(); } else { CP_WAIT0(); }
        __syncthreads();

        const char* base = sm + (s & 1) * 65536;
#pragma unroll
        for (int j = 0; j < 4; ++j) {
            uint32_t aH[4][4], aL[4][4], bH[2][4], bL[2][4];
#pragma unroll
            for (int mi = 0; mi < 4; ++mi) {
                int row = wm * 64 + mi * 16 + (lane & 15);
                int ch  = 2 * j + (lane >> 4);
                uint32_t off = row * 128 + ((ch ^ (row & 7)) << 4);
                ldsm4(aH[mi], smem_u32(base + 0     + off));
                ldsm4(aL[mi], smem_u32(base + 16384 + off));
            }
#pragma unroll
            for (int pi = 0; pi < 2; ++pi) {
                int row = wn * 32 + pi * 16 + (lane & 7) + ((lane & 16) >> 1);
                int ch  = 2 * j + ((lane >> 3) & 1);
                uint32_t off = row * 128 + ((ch ^ (row & 7)) << 4);
                ldsm4(bH[pi], smem_u32(base + 32768 + off));
                ldsm4(bL[pi], smem_u32(base + 49152 + off));
            }
#pragma unroll
            for (int mi = 0; mi < 4; ++mi)
#pragma unroll
                for (int ni = 0; ni < 4; ++ni) {
                    uint32_t bh0 = bH[ni >> 1][(ni & 1) * 2];
                    uint32_t bh1 = bH[ni >> 1][(ni & 1) * 2 + 1];
                    uint32_t bl0 = bL[ni >> 1][(ni & 1) * 2];
                    uint32_t bl1 = bL[ni >> 1][(ni & 1) * 2 + 1];
                    mma16816(cacc[mi][ni], aH[mi], bh0, bh1);
                    mma16816(cacc[mi][ni], aH[mi], bl0, bl1);
                    mma16816(cacc[mi][ni], aL[mi], bh0, bh1);
                }
        }
        __syncthreads();
        if (s + 2 < nstages) LOAD_STAGE(s & 1, s + 2);
    }

    float* cb = C + (size_t)kz * csplit_stride + (size_t)mt * 128 * N4_ + nt * 128;
#pragma unroll
    for (int mi = 0; mi < 4; ++mi)
#pragma unroll
        for (int ni = 0; ni < 4; ++ni) {
            int r   = wm * 64 + mi * 16 + (lane >> 2);
            int col = wn * 32 + ni * 8 + (lane & 3) * 2;
            *(float2*)(cb + (size_t)r * N4_ + col) =
                make_float2(cacc[mi][ni][0], cacc[mi][ni][1]);
            *(float2*)(cb + (size_t)(r + 8) * N4_ + col) =
                make_float2(cacc[mi][ni][2], cacc[mi][ni][3]);
        }
#undef LOAD_STAGE
}

// ---------------- persistent recurrence kernel (one barrier/step) ----------------
// 128 CTAs (1/SM). CTA = (mt 0..3, nt 0..31): tile = 32 batch rows x 128 interleaved
// cols (= 32 units x 4 gates), FULL K=1024 -> complete z in registers -> local eltwise.
// c state lives in registers (each thread owns 4 (b,u) cells for the whole run).
// smem: 4 stage buffers x 40KB {A:h 8KB (hi4K+lo4K), B:W 32KB (hi16K+lo16K)} + zx 16KB.
#define PK_CTAS    128
#define STG_BYTES  40960
#define ZX_OFF     (4 * STG_BYTES)          // 163840
#define PK_SMEM    (ZX_OFF + 16384)         // 180224

__global__ __launch_bounds__(256, 1)
void lstm_persistent(float* __restrict__ out)
{
    extern __shared__ __align__(128) char sm[];

    const int tid  = threadIdx.x;
    const int lane = tid & 31;
    const int wid  = tid >> 5;
    const int wm   = wid & 1;        // 2 warp-rows of 16 m
    const int wn   = wid >> 1;       // 4 warp-cols of 32 n
    const int cta  = blockIdx.x;
    const int nt   = cta & 31;
    const int mt   = cta >> 5;       // 0..3
    const int m0   = mt * 32;

    // eltwise ownership: thread -> (batch row b_r, unit-quad uq)
    const int b_r = tid >> 3;        // 0..31
    const int uq  = tid & 7;         // 0..7
    const int u0  = nt * 32 + uq * 4;

    float4 cst = make_float4(0.f, 0.f, 0.f, 0.f);   // cell state (4 units), in regs

    // issue stage s of step t: A = h[rp] rows m0..m0+32, K slab s*64; B = Wh rows nt*128..
#define ISSUE_STAGE(s, rp) do {                                                     \
        char* buf_ = sm + ((s) & 3) * STG_BYTES;                                    \
        const __nv_bfloat16* hh_ = g_hh[rp];                                        \
        const __nv_bfloat16* hl_ = g_hl[rp];                                        \
        _Pragma("unroll")                                                           \
        for (int i = 0; i < 2; ++i) {        /* A: 512 16B chunks */                \
            int c_ = tid + i * 256;                                                 \
            int pl_ = c_ >> 8, rm_ = c_ & 255, row_ = rm_ >> 3, c8_ = rm_ & 7;      \
            const __nv_bfloat16* src_ = (pl_ ? hl_ : hh_) +                         \
                (size_t)(m0 + row_) * 1024 + (s) * 64 + c8_ * 8;                    \
            uint32_t so_ = pl_ * 4096 + row_ * 128 + ((c8_ ^ (row_ & 7)) << 4);     \
            CP_ASYNC16(smem_u32(buf_ + so_), src_);                                 \
        }                                                                           \
        _Pragma("unroll")                                                           \
        for (int i = 0; i < 8; ++i) {        /* B: 2048 16B chunks */               \
            int c_ = tid + i * 256;                                                 \
            int pl_ = c_ >> 10, rm_ = c_ & 1023, row_ = rm_ >> 3, c8_ = rm_ & 7;    \
            const __nv_bfloat16* src_ = (pl_ ? g_whl : g_whh) +                     \
                (size_t)(nt * 128 + row_) * 1024 + (s) * 64 + c8_ * 8;              \
            uint32_t so_ = 8192 + pl_ * 16384 + row_ * 128 + ((c8_ ^ (row_ & 7)) << 4); \
            CP_ASYNC16(smem_u32(buf_ + so_), src_);                                 \
        }                                                                           \
        CP_COMMIT();                                                                \
    } while (0)

#pragma unroll 1
    for (int t = 1; t < T_; ++t) {
        grid_barrier((unsigned)t * PK_CTAS);   // h[rp] fully written chip-wide
        const int rp = (t - 1) & 1;
        const int wp = t & 1;

        // prologue: zx prefetch (joins stage-0 group) + stages 0..2
        {
            char* zxb = sm + ZX_OFF;
            const float* zxg = g_zx + (size_t)t * B_ * N4_ + nt * 128;
#pragma unroll
            for (int i = 0; i < 4; ++i) {      // 1024 16B chunks
                int c_ = tid + i * 256;
                int row_ = c_ >> 5, c16_ = c_ & 31;
                CP_ASYNC16(smem_u32(zxb + row_ * 512 + c16_ * 16),
                           zxg + (size_t)(m0 + row_) * N4_ + c16_ * 4);
            }
        }
        ISSUE_STAGE(0, rp);                    // commit includes zx
        ISSUE_STAGE(1, rp);
        ISSUE_STAGE(2, rp);

        float cacc[4][4];
#pragma unroll
        for (int ni = 0; ni < 4; ++ni)
#pragma unroll
            for (int q = 0; q < 4; ++q) cacc[ni][q] = 0.0f;

#pragma unroll 1
        for (int s = 0; s < 16; ++s) {
            if (s <= 13) { CP_WAIT2(); } else if (s == 14) { CP_WAIT1(); } else { CP_WAIT0(); }
            __syncthreads();

            const char* base = sm + (s & 3) * STG_BYTES;
#pragma unroll
            for (int j = 0; j < 4; ++j) {
                uint32_t aH[4], aL[4], bH[2][4], bL[2][4];
                {
                    int row = wm * 16 + (lane & 15);
                    int ch  = 2 * j + (lane >> 4);
                    uint32_t off = row * 128 + ((ch ^ (row & 7)) << 4);
                    ldsm4(aH, smem_u32(base + 0    + off));
                    ldsm4(aL, smem_u32(base + 4096 + off));
                }
#pragma unroll
                for (int pi = 0; pi < 2; ++pi) {
                    int row = wn * 32 + pi * 16 + (lane & 7) + ((lane & 16) >> 1);
                    int ch  = 2 * j + ((lane >> 3) & 1);
                    uint32_t off = row * 128 + ((ch ^ (row & 7)) << 4);
                    ldsm4(bH[pi], smem_u32(base + 8192  + off));
                    ldsm4(bL[pi], smem_u32(base + 24576 + off));
                }
#pragma unroll
                for (int ni = 0; ni < 4; ++ni) {
                    uint32_t bh0 = bH[ni >> 1][(ni & 1) * 2];
                    uint32_t bh1 = bH[ni >> 1][(ni & 1) * 2 + 1];
                    uint32_t bl0 = bL[ni >> 1][(ni & 1) * 2];
                    uint32_t bl1 = bL[ni >> 1][(ni & 1) * 2 + 1];
                    mma16816(cacc[ni], aH, bh0, bh1);
                    mma16816(cacc[ni], aH, bl0, bl1);
                    mma16816(cacc[ni], aL, bh0, bh1);
                }
            }
            __syncthreads();
            if (s <= 12) ISSUE_STAGE(s + 3, rp);
        }

        // frag -> smem z staging (32 x 128 fp32, row stride 132 to dodge conflicts)
        {
            float* zbuf = (float*)sm;
#pragma unroll
            for (int ni = 0; ni < 4; ++ni) {
                int r   = wm * 16 + (lane >> 2);
                int col = wn * 32 + ni * 8 + (lane & 3) * 2;
                *(float2*)(zbuf + r * 132 + col)       = make_float2(cacc[ni][0], cacc[ni][1]);
                *(float2*)(zbuf + (r + 8) * 132 + col) = make_float2(cacc[ni][2], cacc[ni][3]);
            }
        }
        __syncthreads();

        // local eltwise: thread owns (b_r, units u0..u0+3)
        {
            const float* zbuf = (const float*)sm;
            const float* zxb  = (const float*)(sm + ZX_OFF);
            float hv[4], cv[4];
#pragma unroll
            for (int j = 0; j < 4; ++j) {
                float4 z  = *(const float4*)(zbuf + b_r * 132 + uq * 16 + j * 4);
                float4 zx = *(const float4*)(zxb + b_r * 128 + uq * 16 + j * 4);
                float4 bb = g_b4[u0 + j];
                float zg = z.x + zx.x + bb.x;
                float zi = z.y + zx.y + bb.y;
                float zf = z.z + zx.z + bb.z;
                float zo = z.w + zx.w + bb.w;
                float g  = tanhf(zg);
                float ii = 1.0f / (1.0f + expf(-zi));
                float f  = 1.0f / (1.0f + expf(-zf));
                float o  = 1.0f / (1.0f + expf(-zo));
                float cprev = (j == 0) ? cst.x : (j == 1) ? cst.y : (j == 2) ? cst.z : cst.w;
                float c  = f * cprev + ii * g;
                cv[j] = c;
                hv[j] = o * tanhf(c);
            }
            cst = make_float4(cv[0], cv[1], cv[2], cv[3]);

            *(float4*)(out + ((size_t)t * B_ + m0 + b_r) * 1024 + u0) =
                make_float4(hv[0], hv[1], hv[2], hv[3]);

            union { __nv_bfloat16 v[4]; uint2 u; } hh, hl;
#pragma unroll
            for (int j = 0; j < 4; ++j) {
                __nv_bfloat16 h = __float2bfloat16(hv[j]);
                hh.v[j] = h;
                hl.v[j] = __float2bfloat16(hv[j] - __bfloat162float(h));
            }
            *(uint2*)(g_hh[wp] + (size_t)(m0 + b_r) * 1024 + u0) = hh.u;
            *(uint2*)(g_hl[wp] + (size_t)(m0 + b_r) * 1024 + u0) = hl.u;
        }
        // h[wp] published by the fence inside next step's grid_barrier
    }
#undef ISSUE_STAGE
}

// ---------------- prep kernels ----------------
__global__ void split_plane(const float* __restrict__ src, __nv_bfloat16* __restrict__ hi,
                            __nv_bfloat16* __restrict__ lo, int n) {
    int i = blockIdx.x * blockDim.x + threadIdx.x;
    if (i < n) {
        float v = src[i];
        __nv_bfloat16 h = __float2bfloat16(v);
        hi[i] = h;
        lo[i] = __float2bfloat16(v - __bfloat162float(h));
    }
}

// gate-INTERLEAVED weight split: dest row = 4*unit + gate
__global__ void split_W(const float* __restrict__ Wg, const float* __restrict__ Wi,
                        const float* __restrict__ Wf, const float* __restrict__ Wo) {
    int idx = blockIdx.x * blockDim.x + threadIdx.x;
    if (idx >= 4 * 1024 * 2048) return;
    int gate = idx >> 21;
    int rem  = idx & ((1 << 21) - 1);
    int n    = rem >> 11;
    int k    = rem & 2047;
    const float* W = (gate == 0) ? Wg : (gate == 1) ? Wi : (gate == 2) ? Wf : Wo;
    float v = W[(size_t)n * 2048 + k];
    __nv_bfloat16 h = __float2bfloat16(v);
    __nv_bfloat16 l = __float2bfloat16(v - __bfloat162float(h));
    int gr = 4 * n + gate;
    if (k < 1024) {
        g_wxh[(size_t)gr * 1024 + k] = h;
        g_wxl[(size_t)gr * 1024 + k] = l;
    } else {
        g_whh[(size_t)gr * 1024 + (k - 1024)] = h;
        g_whl[(size_t)gr * 1024 + (k - 1024)] = l;
    }
}

__global__ void init_state(float* __restrict__ out,
                           const float* __restrict__ bg, const float* __restrict__ bi,
                           const float* __restrict__ bf, const float* __restrict__ bo) {
    int i = blockIdx.x * blockDim.x + threadIdx.x;
    if (i < BH_) {
        out[i] = 0.0f;                          // output[0] = h0 = 0
        g_hh[0][i] = __float2bfloat16(0.0f);    // h_0 planes (read parity of t=1)
        g_hl[0][i] = __float2bfloat16(0.0f);
    }
    if (i < H_) g_b4[i] = make_float4(bg[i], bi[i], bf[i], bo[i]);
    if (i == 0) g_barrier_cnt = 0;              // reset grid barrier each replay
}

// ---------------- launch ----------------
#define GEMM_SMEM (2 * 65536)

extern "C" void kernel_launch(void* const* d_in, const int* in_sizes, int n_in,
                              void* d_out, int out_size)
{
    const float* embeds = (const float*)d_in[0];
    const float* Wg = (const float*)d_in[1];
    const float* Wi = (const float*)d_in[2];
    const float* Wf = (const float*)d_in[3];
    const float* Wo = (const float*)d_in[4];
    const float* bg = (const float*)d_in[5];
    const float* bi = (const float*)d_in[6];
    const float* bf = (const float*)d_in[7];
    const float* bo = (const float*)d_in[8];
    float* out = (float*)d_out;

    cudaFuncSetAttribute(gemm_mma, cudaFuncAttributeMaxDynamicSharedMemorySize, GEMM_SMEM);
    cudaFuncSetAttribute(lstm_persistent, cudaFuncAttributeMaxDynamicSharedMemorySize, PK_SMEM);

    __nv_bfloat16 *p_eh, *p_el, *p_wxh, *p_wxl;
    float *p_zx;
    cudaGetSymbolAddress((void**)&p_eh,  g_eh);
    cudaGetSymbolAddress((void**)&p_el,  g_el);
    cudaGetSymbolAddress((void**)&p_wxh, g_wxh);
    cudaGetSymbolAddress((void**)&p_wxl, g_wxl);
    cudaGetSymbolAddress((void**)&p_zx,  g_zx);

    // prep
    {
        int n = T_ * B_ * E_;
        split_plane<<<(n + 255) / 256, 256>>>(embeds, p_eh, p_el, n);
    }
    split_W<<<(4 * 1024 * 2048 + 255) / 256, 256>>>(Wg, Wi, Wf, Wo);
    init_state<<<(BH_ + 255) / 256, 256>>>(out, bg, bi, bf, bo);

    // batch: Zx[t] = x_t @ Wx'^T for all t (interleaved cols)
    gemm_mma<<<dim3(32, 256, 1), 256, GEMM_SMEM>>>(p_eh, p_el, 1024, p_wxh, p_wxl,
                                                   p_zx, 0, 1024);

    // recurrence: one persistent kernel, one barrier per step
    lstm_persistent<<<PK_CTAS, 256, PK_SMEM>>>(out);
}

// round 8
// speedup vs baseline: 1.4203x; 1.0456x over previous
#include <cuda_runtime.h>
#include <cuda_bf16.h>
#include <cstdint>

// ---------------- problem constants ----------------
#define T_    256
#define B_    128
#define E_    1024
#define H_    1024
#define N4_   4096
#define BH_   (B_ * H_)
#define NSPLIT 4

// ---------------- static device scratch ----------------
// weights / z use GATE-INTERLEAVED column order: col' = 4*unit + gate
__device__ float          g_zx[(size_t)T_ * B_ * N4_];   // x-part preactivations (interleaved)
__device__ float          g_zh[NSPLIT * B_ * N4_];       // per-step h-part partials
__device__ float4         g_b4[H_];                      // interleaved bias {bg,bi,bf,bo}[u]
__device__ __nv_bfloat16  g_eh[(size_t)T_ * B_ * E_];    // embeds hi
__device__ __nv_bfloat16  g_el[(size_t)T_ * B_ * E_];    // embeds lo
__device__ __nv_bfloat16  g_wxh[N4_ * 1024];             // Wx hi (interleaved rows, K-major)
__device__ __nv_bfloat16  g_wxl[N4_ * 1024];
__device__ __nv_bfloat16  g_whh[N4_ * 1024];             // Wh hi (interleaved rows)
__device__ __nv_bfloat16  g_whl[N4_ * 1024];
__device__ __nv_bfloat16  g_hh[2][BH_];                  // h double buffer, hi plane
__device__ __nv_bfloat16  g_hl[2][BH_];                  // h double buffer, lo plane
__device__ unsigned       g_barrier_cnt;                 // grid barrier (monotonic)
__device__ unsigned       g_pcnt[32];                    // per-nt partial counters (monotonic)

// ---------------- arch-generic PTX helpers ----------------
__device__ __forceinline__ uint32_t smem_u32(const void* p) {
    uint32_t a;
    asm("{ .reg .u64 t; cvta.to.shared.u64 t, %1; cvt.u32.u64 %0, t; }" : "=r"(a) : "l"(p));
    return a;
}
__device__ __forceinline__ void ldsm4(uint32_t r[4], uint32_t saddr) {
    asm volatile("ldmatrix.sync.aligned.m8n8.x4.shared.b16 {%0,%1,%2,%3}, [%4];"
                 : "=r"(r[0]), "=r"(r[1]), "=r"(r[2]), "=r"(r[3]) : "r"(saddr));
}
__device__ __forceinline__ void mma16816(float c[4], const uint32_t a[4],
                                         uint32_t b0, uint32_t b1) {
    asm volatile("mma.sync.aligned.m16n8k16.row.col.f32.bf16.bf16.f32 "
                 "{%0,%1,%2,%3}, {%4,%5,%6,%7}, {%8,%9}, {%0,%1,%2,%3};"
                 : "+f"(c[0]), "+f"(c[1]), "+f"(c[2]), "+f"(c[3])
                 : "r"(a[0]), "r"(a[1]), "r"(a[2]), "r"(a[3]), "r"(b0), "r"(b1));
}
#define CP_ASYNC16(dst, src) \
    asm volatile("cp.async.cg.shared.global [%0], [%1], 16;" :: "r"(dst), "l"(src))
#define CP_COMMIT() asm volatile("cp.async.commit_group;" ::: "memory")
#define CP_WAIT0()  asm volatile("cp.async.wait_group 0;" ::: "memory")
#define CP_WAIT1()  asm volatile("cp.async.wait_group 1;" ::: "memory")

// ---------------- grid barrier (all 128 CTAs co-resident) ----------------
__device__ __forceinline__ void grid_barrier(unsigned target) {
    __threadfence();
    __syncthreads();
    if (threadIdx.x == 0) {
        atomicAdd(&g_barrier_cnt, 1u);
        while (*(volatile unsigned*)&g_barrier_cnt < target) { }
        __threadfence();
    }
    __syncthreads();
}

// ---------------- batch 3-plane bf16 GEMM (3-stage pipeline, 1 sync/stage) ----------------
__global__ __launch_bounds__(256, 1)
void gemm_mma(const __nv_bfloat16* __restrict__ Ah, const __nv_bfloat16* __restrict__ Al,
              int lda,
              const __nv_bfloat16* __restrict__ Bh, const __nv_bfloat16* __restrict__ Bl,
              float* __restrict__ C, size_t csplit_stride, int klen)
{
    extern __shared__ __align__(128) char sm[];

    const int tid  = threadIdx.x;
    const int lane = tid & 31;
    const int wid  = tid >> 5;
    const int wm   = wid & 1;
    const int wn   = wid >> 1;
    const int nt = blockIdx.x, mt = blockIdx.y, kz = blockIdx.z;
    const int kofs = kz * klen;
    const int nstages = klen >> 6;

    const __nv_bfloat16* a_h = Ah + (size_t)mt * 128 * lda + kofs;
    const __nv_bfloat16* a_l = Al + (size_t)mt * 128 * lda + kofs;
    const __nv_bfloat16* b_h = Bh + (size_t)nt * 128 * 1024 + kofs;
    const __nv_bfloat16* b_l = Bl + (size_t)nt * 128 * 1024 + kofs;

    const int lrow = tid >> 3;
    const int lc   = tid & 7;

#define LOAD_STAGE(buf, s) do {                                                    \
        char* dst_ = sm + (buf) * 65536;                                           \
        const __nv_bfloat16* s0_ = a_h + (s) * 64;                                 \
        const __nv_bfloat16* s1_ = a_l + (s) * 64;                                 \
        const __nv_bfloat16* s2_ = b_h + (s) * 64;                                 \
        const __nv_bfloat16* s3_ = b_l + (s) * 64;                                 \
        _Pragma("unroll")                                                          \
        for (int p = 0; p < 4; ++p) {                                              \
            int row = lrow + p * 32;                                               \
            uint32_t so = row * 128 + ((lc ^ (row & 7)) << 4);                     \
            CP_ASYNC16(smem_u32(dst_ + 0     + so), s0_ + (size_t)row * lda + lc * 8); \
            CP_ASYNC16(smem_u32(dst_ + 16384 + so), s1_ + (size_t)row * lda + lc * 8); \
            CP_ASYNC16(smem_u32(dst_ + 32768 + so), s2_ + (size_t)row * 1024 + lc * 8); \
            CP_ASYNC16(smem_u32(dst_ + 49152 + so), s3_ + (size_t)row * 1024 + lc * 8); \
        }                                                                          \
        CP_COMMIT();                                                               \
    } while (0)

    float cacc[4][4][4];
#pragma unroll
    for (int mi = 0; mi < 4; ++mi)
#pragma unroll
        for (int ni = 0; ni < 4; ++ni)
#pragma unroll
            for (int q = 0; q < 4; ++q) cacc[mi][ni][q] = 0.0f;

    LOAD_STAGE(0, 0);
    if (nstages > 1) LOAD_STAGE(1, 1);

#pragma unroll 1
    for (int s = 0; s < nstages; ++s) {
        if (s + 1 < nstages) { CP_WAIT1(); } else { CP_WAIT0(); }
        __syncthreads();

        const char* base = sm + (s % 3) * 65536;
#pragma unroll
        for (int j = 0; j < 4; ++j) {
            uint32_t aH[4][4], aL[4][4], bH[2][4], bL[2][4];
#pragma unroll
            for (int mi = 0; mi < 4; ++mi) {
                int row = wm * 64 + mi * 16 + (lane & 15);
                int ch  = 2 * j + (lane >> 4);
                uint32_t off = row * 128 + ((ch ^ (row & 7)) << 4);
                ldsm4(aH[mi], smem_u32(base + 0     + off));
                ldsm4(aL[mi], smem_u32(base + 16384 + off));
            }
#pragma unroll
            for (int pi = 0; pi < 2; ++pi) {
                int row = wn * 32 + pi * 16 + (lane & 7) + ((lane & 16) >> 1);
                int ch  = 2 * j + ((lane >> 3) & 1);
                uint32_t off = row * 128 + ((ch ^ (row & 7)) << 4);
                ldsm4(bH[pi], smem_u32(base + 32768 + off));
                ldsm4(bL[pi], smem_u32(base + 49152 + off));
            }
#pragma unroll
            for (int mi = 0; mi < 4; ++mi)
#pragma unroll
                for (int ni = 0; ni < 4; ++ni) {
                    uint32_t bh0 = bH[ni >> 1][(ni & 1) * 2];
                    uint32_t bh1 = bH[ni >> 1][(ni & 1) * 2 + 1];
                    uint32_t bl0 = bL[ni >> 1][(ni & 1) * 2];
                    uint32_t bl1 = bL[ni >> 1][(ni & 1) * 2 + 1];
                    mma16816(cacc[mi][ni], aH[mi], bh0, bh1);
                    mma16816(cacc[mi][ni], aH[mi], bl0, bl1);
                    mma16816(cacc[mi][ni], aL[mi], bh0, bh1);
                }
        }
        // 3-stage rotation: refill targets the buffer last read 2 stages ago,
        // every thread has passed a __syncthreads since -> no post-compute sync.
        if (s + 2 < nstages) LOAD_STAGE((s + 2) % 3, s + 2);
    }

    float* cb = C + (size_t)kz * csplit_stride + (size_t)mt * 128 * N4_ + nt * 128;
#pragma unroll
    for (int mi = 0; mi < 4; ++mi)
#pragma unroll
        for (int ni = 0; ni < 4; ++ni) {
            int r   = wm * 64 + mi * 16 + (lane >> 2);
            int col = wn * 32 + ni * 8 + (lane & 3) * 2;
            *(float2*)(cb + (size_t)r * N4_ + col) =
                make_float2(cacc[mi][ni][0], cacc[mi][ni][1]);
            *(float2*)(cb + (size_t)(r + 8) * N4_ + col) =
                make_float2(cacc[mi][ni][2], cacc[mi][ni][3]);
        }
#undef LOAD_STAGE
}

// ---------------- persistent recurrence kernel ----------------
// 128 CTAs x 512 threads. CTA = (nt 0..31, kz 0..3). Resident Wh slab (128KB),
// streamed h (3-buffer), one global barrier + per-nt flag sync, c in registers.
// smem: [0,64K) Whi[s], [64K,128K) Wlo[s], [128K, 128K+3*32K) h stage buffers.
#define PK_CTAS   128
#define PK_THREADS 512
#define SM_WHI(s)   (sm + (s) * 16384)
#define SM_WLO(s)   (sm + 65536 + (s) * 16384)
#define SM_HBUF(b)  (sm + 131072 + (b) * 32768)
#define PK_SMEM     (131072 + 3 * 32768)      // 229376

__global__ __launch_bounds__(PK_THREADS, 1)
void lstm_persistent(float* __restrict__ out)
{
    extern __shared__ __align__(128) char sm[];

    const int tid  = threadIdx.x;
    const int lane = tid & 31;
    const int wid  = tid >> 5;
    const int wm   = wid & 3;        // 4 warp-rows of 32 m
    const int wn   = wid >> 2;       // 4 warp-cols of 32 n
    const int cta  = blockIdx.x;
    const int nt   = cta & 31;
    const int kz   = cta >> 5;

    // eltwise ownership: rows kz*32 + b_r, unit-pair uh (2 units x 4 gates)
    const int b_r = tid >> 4;        // 0..31
    const int uh  = tid & 15;        // 0..15
    const int gr  = kz * 32 + b_r;   // global batch row
    const int u0  = nt * 32 + uh * 2;

    float c0 = 0.0f, c1 = 0.0f;      // resident cell state (2 units)

    // ---- resident W slab: 4 K64 sub-slabs, hi+lo (one cp.async group) ----
#pragma unroll
    for (int sub = 0; sub < 4; ++sub) {
#pragma unroll
        for (int i = 0; i < 4; ++i) {
            int c_ = tid + i * 512;                 // 0..2047
            int pl = c_ >> 10, rm = c_ & 1023, row = rm >> 3, c8 = rm & 7;
            const __nv_bfloat16* src = (pl ? g_whl : g_whh) +
                (size_t)(nt * 128 + row) * 1024 + kz * 256 + sub * 64 + c8 * 8;
            uint32_t so = row * 128 + ((c8 ^ (row & 7)) << 4);
            CP_ASYNC16(smem_u32((pl ? SM_WLO(sub) : SM_WHI(sub)) + so), src);
        }
    }
    CP_COMMIT();

#define LOADH(buf, s, rp) do {                                                      \
        char* dst_ = SM_HBUF(buf);                                                  \
        const __nv_bfloat16* hh_ = g_hh[rp];                                        \
        const __nv_bfloat16* hl_ = g_hl[rp];                                        \
        _Pragma("unroll")                                                           \
        for (int i = 0; i < 4; ++i) {                                               \
            int c_ = tid + i * 512;                                                 \
            int pl_ = c_ >> 10, rm_ = c_ & 1023, row_ = rm_ >> 3, c8_ = rm_ & 7;    \
            const __nv_bfloat16* src_ = (pl_ ? hl_ : hh_) +                         \
                (size_t)row_ * 1024 + kz * 256 + (s) * 64 + c8_ * 8;                \
            uint32_t so_ = pl_ * 16384 + row_ * 128 + ((c8_ ^ (row_ & 7)) << 4);    \
            CP_ASYNC16(smem_u32(dst_ + so_), src_);                                 \
        }                                                                           \
        CP_COMMIT();                                                                \
    } while (0)

#pragma unroll 1
    for (int t = 1; t < T_; ++t) {
        grid_barrier((unsigned)t * PK_CTAS);       // h[rp] complete chip-wide
        const int rp = (t - 1) & 1;
        const int wp = t & 1;

        LOADH(0, 0, rp);
        LOADH(1, 1, rp);

        float cacc[2][4][4];
#pragma unroll
        for (int mi = 0; mi < 2; ++mi)
#pragma unroll
            for (int ni = 0; ni < 4; ++ni)
#pragma unroll
                for (int q = 0; q < 4; ++q) cacc[mi][ni][q] = 0.0f;

#pragma unroll 1
        for (int s = 0; s < 4; ++s) {
            if (s < 3) { CP_WAIT1(); } else { CP_WAIT0(); }
            __syncthreads();

            const char* abase  = SM_HBUF(s % 3);
            const char* bhbase = SM_WHI(s);
            const char* blbase = SM_WLO(s);
#pragma unroll
            for (int j = 0; j < 4; ++j) {
                uint32_t aH[2][4], aL[2][4], bH[2][4], bL[2][4];
#pragma unroll
                for (int mi = 0; mi < 2; ++mi) {
                    int row = wm * 32 + mi * 16 + (lane & 15);
                    int ch  = 2 * j + (lane >> 4);
                    uint32_t off = row * 128 + ((ch ^ (row & 7)) << 4);
                    ldsm4(aH[mi], smem_u32(abase + off));
                    ldsm4(aL[mi], smem_u32(abase + 16384 + off));
                }
#pragma unroll
                for (int pi = 0; pi < 2; ++pi) {
                    int row = wn * 32 + pi * 16 + (lane & 7) + ((lane & 16) >> 1);
                    int ch  = 2 * j + ((lane >> 3) & 1);
                    uint32_t off = row * 128 + ((ch ^ (row & 7)) << 4);
                    ldsm4(bH[pi], smem_u32(bhbase + off));
                    ldsm4(bL[pi], smem_u32(blbase + off));
                }
#pragma unroll
                for (int mi = 0; mi < 2; ++mi)
#pragma unroll
                    for (int ni = 0; ni < 4; ++ni) {
                        uint32_t bh0 = bH[ni >> 1][(ni & 1) * 2];
                        uint32_t bh1 = bH[ni >> 1][(ni & 1) * 2 + 1];
                        uint32_t bl0 = bL[ni >> 1][(ni & 1) * 2];
                        uint32_t bl1 = bL[ni >> 1][(ni & 1) * 2 + 1];
                        mma16816(cacc[mi][ni], aH[mi], bh0, bh1);
                        mma16816(cacc[mi][ni], aH[mi], bl0, bl1);
                        mma16816(cacc[mi][ni], aL[mi], bh0, bh1);
                    }
            }
            if (s + 2 < 4) LOADH((s + 2) % 3, s + 2, rp);
        }

        // ---- write z partials (this CTA's kz slab, its 128 cols) ----
        {
            float* cb = g_zh + (size_t)kz * (B_ * N4_) + nt * 128;
#pragma unroll
            for (int mi = 0; mi < 2; ++mi)
#pragma unroll
                for (int ni = 0; ni < 4; ++ni) {
                    int r   = wm * 32 + mi * 16 + (lane >> 2);
                    int col = wn * 32 + ni * 8 + (lane & 3) * 2;
                    *(float2*)(cb + (size_t)r * N4_ + col) =
                        make_float2(cacc[mi][ni][0], cacc[mi][ni][1]);
                    *(float2*)(cb + (size_t)(r + 8) * N4_ + col) =
                        make_float2(cacc[mi][ni][2], cacc[mi][ni][3]);
                }
        }
        __threadfence();                 // publish partials (all threads)
        __syncthreads();
        if (tid == 0) {
            atomicAdd(&g_pcnt[nt], 1u);
            unsigned tgt = 4u * (unsigned)t;    // all 4 kz CTAs of group nt
            while (*(volatile unsigned*)&g_pcnt[nt] < tgt) { }
            __threadfence();
        }
        __syncthreads();

        // ---- local eltwise: rows kz*32.., this nt's 32 units ----
        {
            size_t rowoff = (size_t)gr * N4_ + nt * 128 + uh * 8;
            const float4* px = (const float4*)(g_zx + (size_t)t * B_ * N4_ + rowoff);
            float4 z0 = __ldg(px + 0);
            float4 z1 = __ldg(px + 1);
#pragma unroll
            for (int kzi = 0; kzi < NSPLIT; ++kzi) {
                const float4* pp = (const float4*)(g_zh + (size_t)kzi * (B_ * N4_) + rowoff);
                float4 a0 = __ldcg(pp + 0), a1 = __ldcg(pp + 1);
                z0.x += a0.x; z0.y += a0.y; z0.z += a0.z; z0.w += a0.w;
                z1.x += a1.x; z1.y += a1.y; z1.z += a1.z; z1.w += a1.w;
            }
            float4 bb0 = g_b4[u0];
            float4 bb1 = g_b4[u0 + 1];

            float hv[2];
            {
                float zg = z0.x + bb0.x, zi = z0.y + bb0.y;
                float zf = z0.z + bb0.z, zo = z0.w + bb0.w;
                float g  = tanhf(zg);
                float ii = 1.0f / (1.0f + expf(-zi));
                float f  = 1.0f / (1.0f + expf(-zf));
                float o  = 1.0f / (1.0f + expf(-zo));
                c0 = f * c0 + ii * g;
                hv[0] = o * tanhf(c0);
            }
            {
                float zg = z1.x + bb1.x, zi = z1.y + bb1.y;
                float zf = z1.z + bb1.z, zo = z1.w + bb1.w;
                float g  = tanhf(zg);
                float ii = 1.0f / (1.0f + expf(-zi));
                float f  = 1.0f / (1.0f + expf(-zf));
                float o  = 1.0f / (1.0f + expf(-zo));
                c1 = f * c1 + ii * g;
                hv[1] = o * tanhf(c1);
            }

            *(float2*)(out + ((size_t)t * B_ + gr) * 1024 + u0) = make_float2(hv[0], hv[1]);

            union { __nv_bfloat16 v[2]; uint32_t u; } hh, hl;
            __nv_bfloat16 h0 = __float2bfloat16(hv[0]);
            __nv_bfloat16 h1 = __float2bfloat16(hv[1]);
            hh.v[0] = h0; hh.v[1] = h1;
            hl.v[0] = __float2bfloat16(hv[0] - __bfloat162float(h0));
            hl.v[1] = __float2bfloat16(hv[1] - __bfloat162float(h1));
            *(uint32_t*)(g_hh[wp] + (size_t)gr * 1024 + u0) = hh.u;
            *(uint32_t*)(g_hl[wp] + (size_t)gr * 1024 + u0) = hl.u;
        }
        // h[wp] published by the fence inside next step's grid_barrier
    }
#undef LOADH
}

// ---------------- prep kernels ----------------
__global__ void split_plane(const float* __restrict__ src, __nv_bfloat16* __restrict__ hi,
                            __nv_bfloat16* __restrict__ lo, int n) {
    int i = blockIdx.x * blockDim.x + threadIdx.x;
    if (i < n) {
        float v = src[i];
        __nv_bfloat16 h = __float2bfloat16(v);
        hi[i] = h;
        lo[i] = __float2bfloat16(v - __bfloat162float(h));
    }
}

// gate-INTERLEAVED weight split: dest row = 4*unit + gate
__global__ void split_W(const float* __restrict__ Wg, const float* __restrict__ Wi,
                        const float* __restrict__ Wf, const float* __restrict__ Wo) {
    int idx = blockIdx.x * blockDim.x + threadIdx.x;
    if (idx >= 4 * 1024 * 2048) return;
    int gate = idx >> 21;
    int rem  = idx & ((1 << 21) - 1);
    int n    = rem >> 11;
    int k    = rem & 2047;
    const float* W = (gate == 0) ? Wg : (gate == 1) ? Wi : (gate == 2) ? Wf : Wo;
    float v = W[(size_t)n * 2048 + k];
    __nv_bfloat16 h = __float2bfloat16(v);
    __nv_bfloat16 l = __float2bfloat16(v - __bfloat162float(h));
    int gr = 4 * n + gate;
    if (k < 1024) {
        g_wxh[(size_t)gr * 1024 + k] = h;
        g_wxl[(size_t)gr * 1024 + k] = l;
    } else {
        g_whh[(size_t)gr * 1024 + (k - 1024)] = h;
        g_whl[(size_t)gr * 1024 + (k - 1024)] = l;
    }
}

__global__ void init_state(float* __restrict__ out,
                           const float* __restrict__ bg, const float* __restrict__ bi,
                           const float* __restrict__ bf, const float* __restrict__ bo) {
    int i = blockIdx.x * blockDim.x + threadIdx.x;
    if (i < BH_) {
        out[i] = 0.0f;                          // output[0] = h0 = 0
        g_hh[0][i] = __float2bfloat16(0.0f);    // h_0 planes (parity read at t=1)
        g_hl[0][i] = __float2bfloat16(0.0f);
    }
    if (i < H_) g_b4[i] = make_float4(bg[i], bi[i], bf[i], bo[i]);
    if (i < 32) g_pcnt[i] = 0;
    if (i == 0) g_barrier_cnt = 0;
}

// ---------------- launch ----------------
#define GEMM_SMEM (3 * 65536)

extern "C" void kernel_launch(void* const* d_in, const int* in_sizes, int n_in,
                              void* d_out, int out_size)
{
    const float* embeds = (const float*)d_in[0];
    const float* Wg = (const float*)d_in[1];
    const float* Wi = (const float*)d_in[2];
    const float* Wf = (const float*)d_in[3];
    const float* Wo = (const float*)d_in[4];
    const float* bg = (const float*)d_in[5];
    const float* bi = (const float*)d_in[6];
    const float* bf = (const float*)d_in[7];
    const float* bo = (const float*)d_in[8];
    float* out = (float*)d_out;

    cudaFuncSetAttribute(gemm_mma, cudaFuncAttributeMaxDynamicSharedMemorySize, GEMM_SMEM);
    cudaFuncSetAttribute(lstm_persistent, cudaFuncAttributeMaxDynamicSharedMemorySize, PK_SMEM);

    __nv_bfloat16 *p_eh, *p_el, *p_wxh, *p_wxl;
    float *p_zx;
    cudaGetSymbolAddress((void**)&p_eh,  g_eh);
    cudaGetSymbolAddress((void**)&p_el,  g_el);
    cudaGetSymbolAddress((void**)&p_wxh, g_wxh);
    cudaGetSymbolAddress((void**)&p_wxl, g_wxl);
    cudaGetSymbolAddress((void**)&p_zx,  g_zx);

    // prep
    {
        int n = T_ * B_ * E_;
        split_plane<<<(n + 255) / 256, 256>>>(embeds, p_eh, p_el, n);
    }
    split_W<<<(4 * 1024 * 2048 + 255) / 256, 256>>>(Wg, Wi, Wf, Wo);
    init_state<<<(BH_ + 255) / 256, 256>>>(out, bg, bi, bf, bo);

    // batch: Zx[t] = x_t @ Wx'^T for all t (interleaved cols)
    gemm_mma<<<dim3(32, 256, 1), 256, GEMM_SMEM>>>(p_eh, p_el, 1024, p_wxh, p_wxl,
                                                   p_zx, 0, 1024);

    // recurrence: one persistent kernel
    lstm_persistent<<<PK_CTAS, PK_THREADS, PK_SMEM>>>(out);
}

// round 9
// speedup vs baseline: 1.4284x; 1.0057x over previous
#include <cuda_runtime.h>
#include <cuda_bf16.h>
#include <cstdint>

// ---------------- problem constants ----------------
#define T_    256
#define B_    128
#define E_    1024
#define H_    1024
#define N4_   4096
#define BH_   (B_ * H_)
#define NSPLIT 4

// ---------------- static device scratch ----------------
// weights / z use GATE-INTERLEAVED column order: col' = 4*unit + gate
__device__ float          g_zx[(size_t)T_ * B_ * N4_];   // x-part preactivations (interleaved)
__device__ float          g_zh[NSPLIT * B_ * N4_];       // per-step h-part partials
__device__ float4         g_b4[H_];                      // interleaved bias {bg,bi,bf,bo}[u]
__device__ __nv_bfloat16  g_eh[(size_t)T_ * B_ * E_];    // embeds hi
__device__ __nv_bfloat16  g_el[(size_t)T_ * B_ * E_];    // embeds lo
__device__ __nv_bfloat16  g_wxh[N4_ * 1024];             // Wx hi (interleaved rows, K-major)
__device__ __nv_bfloat16  g_wxl[N4_ * 1024];
__device__ __nv_bfloat16  g_whh[N4_ * 1024];             // Wh hi (interleaved rows)
__device__ __nv_bfloat16  g_whl[N4_ * 1024];
__device__ __nv_bfloat16  g_hh[3][BH_];                  // h triple buffer, hi plane
__device__ __nv_bfloat16  g_hl[3][BH_];                  // h triple buffer, lo plane
__device__ unsigned       g_hcnt[4];                     // per-region h-ready counters (monotonic)
__device__ unsigned       g_pcnt[32];                    // per-nt partial counters (monotonic)

// ---------------- arch-generic PTX helpers ----------------
__device__ __forceinline__ uint32_t smem_u32(const void* p) {
    uint32_t a;
    asm("{ .reg .u64 t; cvta.to.shared.u64 t, %1; cvt.u32.u64 %0, t; }" : "=r"(a) : "l"(p));
    return a;
}
__device__ __forceinline__ void ldsm4(uint32_t r[4], uint32_t saddr) {
    asm volatile("ldmatrix.sync.aligned.m8n8.x4.shared.b16 {%0,%1,%2,%3}, [%4];"
                 : "=r"(r[0]), "=r"(r[1]), "=r"(r[2]), "=r"(r[3]) : "r"(saddr));
}
__device__ __forceinline__ void mma16816(float c[4], const uint32_t a[4],
                                         uint32_t b0, uint32_t b1) {
    asm volatile("mma.sync.aligned.m16n8k16.row.col.f32.bf16.bf16.f32 "
                 "{%0,%1,%2,%3}, {%4,%5,%6,%7}, {%8,%9}, {%0,%1,%2,%3};"
                 : "+f"(c[0]), "+f"(c[1]), "+f"(c[2]), "+f"(c[3])
                 : "r"(a[0]), "r"(a[1]), "r"(a[2]), "r"(a[3]), "r"(b0), "r"(b1));
}
#define CP_ASYNC16(dst, src) \
    asm volatile("cp.async.cg.shared.global [%0], [%1], 16;" :: "r"(dst), "l"(src))
#define CP_COMMIT() asm volatile("cp.async.commit_group;" ::: "memory")
#define CP_WAIT0()  asm volatile("cp.async.wait_group 0;" ::: "memory")
#define CP_WAIT1()  asm volatile("cp.async.wait_group 1;" ::: "memory")

// ---------------- batch 3-plane bf16 GEMM (3-stage pipeline, known-good) ----------------
__global__ __launch_bounds__(256, 1)
void gemm_mma(const __nv_bfloat16* __restrict__ Ah, const __nv_bfloat16* __restrict__ Al,
              int lda,
              const __nv_bfloat16* __restrict__ Bh, const __nv_bfloat16* __restrict__ Bl,
              float* __restrict__ C, size_t csplit_stride, int klen)
{
    extern __shared__ __align__(128) char sm[];

    const int tid  = threadIdx.x;
    const int lane = tid & 31;
    const int wid  = tid >> 5;
    const int wm   = wid & 1;
    const int wn   = wid >> 1;
    const int nt = blockIdx.x, mt = blockIdx.y, kz = blockIdx.z;
    const int kofs = kz * klen;
    const int nstages = klen >> 6;

    const __nv_bfloat16* a_h = Ah + (size_t)mt * 128 * lda + kofs;
    const __nv_bfloat16* a_l = Al + (size_t)mt * 128 * lda + kofs;
    const __nv_bfloat16* b_h = Bh + (size_t)nt * 128 * 1024 + kofs;
    const __nv_bfloat16* b_l = Bl + (size_t)nt * 128 * 1024 + kofs;

    const int lrow = tid >> 3;
    const int lc   = tid & 7;

#define LOAD_STAGE(buf, s) do {                                                    \
        char* dst_ = sm + (buf) * 65536;                                           \
        const __nv_bfloat16* s0_ = a_h + (s) * 64;                                 \
        const __nv_bfloat16* s1_ = a_l + (s) * 64;                                 \
        const __nv_bfloat16* s2_ = b_h + (s) * 64;                                 \
        const __nv_bfloat16* s3_ = b_l + (s) * 64;                                 \
        _Pragma("unroll")                                                          \
        for (int p = 0; p < 4; ++p) {                                              \
            int row = lrow + p * 32;                                               \
            uint32_t so = row * 128 + ((lc ^ (row & 7)) << 4);                     \
            CP_ASYNC16(smem_u32(dst_ + 0     + so), s0_ + (size_t)row * lda + lc * 8); \
            CP_ASYNC16(smem_u32(dst_ + 16384 + so), s1_ + (size_t)row * lda + lc * 8); \
            CP_ASYNC16(smem_u32(dst_ + 32768 + so), s2_ + (size_t)row * 1024 + lc * 8); \
            CP_ASYNC16(smem_u32(dst_ + 49152 + so), s3_ + (size_t)row * 1024 + lc * 8); \
        }                                                                          \
        CP_COMMIT();                                                               \
    } while (0)

    float cacc[4][4][4];
#pragma unroll
    for (int mi = 0; mi < 4; ++mi)
#pragma unroll
        for (int ni = 0; ni < 4; ++ni)
#pragma unroll
            for (int q = 0; q < 4; ++q) cacc[mi][ni][q] = 0.0f;

    LOAD_STAGE(0, 0);
    if (nstages > 1) LOAD_STAGE(1, 1);

#pragma unroll 1
    for (int s = 0; s < nstages; ++s) {
        if (s + 1 < nstages) { CP_WAIT1(); } else { CP_WAIT0(); }
        __syncthreads();

        const char* base = sm + (s % 3) * 65536;
#pragma unroll
        for (int j = 0; j < 4; ++j) {
            uint32_t aH[4][4], aL[4][4], bH[2][4], bL[2][4];
#pragma unroll
            for (int mi = 0; mi < 4; ++mi) {
                int row = wm * 64 + mi * 16 + (lane & 15);
                int ch  = 2 * j + (lane >> 4);
                uint32_t off = row * 128 + ((ch ^ (row & 7)) << 4);
                ldsm4(aH[mi], smem_u32(base + 0     + off));
                ldsm4(aL[mi], smem_u32(base + 16384 + off));
            }
#pragma unroll
            for (int pi = 0; pi < 2; ++pi) {
                int row = wn * 32 + pi * 16 + (lane & 7) + ((lane & 16) >> 1);
                int ch  = 2 * j + ((lane >> 3) & 1);
                uint32_t off = row * 128 + ((ch ^ (row & 7)) << 4);
                ldsm4(bH[pi], smem_u32(base + 32768 + off));
                ldsm4(bL[pi], smem_u32(base + 49152 + off));
            }
#pragma unroll
            for (int mi = 0; mi < 4; ++mi)
#pragma unroll
                for (int ni = 0; ni < 4; ++ni) {
                    uint32_t bh0 = bH[ni >> 1][(ni & 1) * 2];
                    uint32_t bh1 = bH[ni >> 1][(ni & 1) * 2 + 1];
                    uint32_t bl0 = bL[ni >> 1][(ni & 1) * 2];
                    uint32_t bl1 = bL[ni >> 1][(ni & 1) * 2 + 1];
                    mma16816(cacc[mi][ni], aH[mi], bh0, bh1);
                    mma16816(cacc[mi][ni], aH[mi], bl0, bl1);
                    mma16816(cacc[mi][ni], aL[mi], bh0, bh1);
                }
        }
        if (s + 2 < nstages) LOAD_STAGE((s + 2) % 3, s + 2);
    }

    float* cb = C + (size_t)kz * csplit_stride + (size_t)mt * 128 * N4_ + nt * 128;
#pragma unroll
    for (int mi = 0; mi < 4; ++mi)
#pragma unroll
        for (int ni = 0; ni < 4; ++ni) {
            int r   = wm * 64 + mi * 16 + (lane >> 2);
            int col = wn * 32 + ni * 8 + (lane & 3) * 2;
            *(float2*)(cb + (size_t)r * N4_ + col) =
                make_float2(cacc[mi][ni][0], cacc[mi][ni][1]);
            *(float2*)(cb + (size_t)(r + 8) * N4_ + col) =
                make_float2(cacc[mi][ni][2], cacc[mi][ni][3]);
        }
#undef LOAD_STAGE
}

// ---------------- persistent recurrence kernel (region-flag pipeline) ----------------
// 128 CTAs x 512 threads. CTA = (nt 0..31, kz 0..3). Resident Wh slab (128KB),
// streamed h (3-buffer smem), producer/consumer region flags, c in registers.
// Region r covers h units produced by nt' in [8r, 8r+8). Consumer (nt,kz) waits
// region kz (its GEMM input) and region nt>>3 (protects its zh slot + h slot reuse).
#define PK_CTAS   128
#define PK_THREADS 512
#define SM_WHI(s)   (sm + (s) * 16384)
#define SM_WLO(s)   (sm + 65536 + (s) * 16384)
#define SM_HBUF(b)  (sm + 131072 + (b) * 32768)
#define PK_SMEM     (131072 + 3 * 32768)      // 229376

__global__ __launch_bounds__(PK_THREADS, 1)
void lstm_persistent(float* __restrict__ out)
{
    extern __shared__ __align__(128) char sm[];

    const int tid  = threadIdx.x;
    const int lane = tid & 31;
    const int wid  = tid >> 5;
    const int wm   = wid & 3;        // 4 warp-rows of 32 m
    const int wn   = wid >> 2;       // 4 warp-cols of 32 n
    const int cta  = blockIdx.x;
    const int nt   = cta & 31;
    const int kz   = cta >> 5;
    const int reg_own = nt >> 3;     // region this CTA's h output belongs to

    // eltwise ownership: rows kz*32 + b_r, unit-pair uh
    const int b_r = tid >> 4;
    const int uh  = tid & 15;
    const int gr  = kz * 32 + b_r;
    const int u0  = nt * 32 + uh * 2;

    float c0 = 0.0f, c1 = 0.0f;      // resident cell state

    // ---- resident W slab: 4 K64 sub-slabs, hi+lo ----
#pragma unroll
    for (int sub = 0; sub < 4; ++sub) {
#pragma unroll
        for (int i = 0; i < 4; ++i) {
            int c_ = tid + i * 512;
            int pl = c_ >> 10, rm = c_ & 1023, row = rm >> 3, c8 = rm & 7;
            const __nv_bfloat16* src = (pl ? g_whl : g_whh) +
                (size_t)(nt * 128 + row) * 1024 + kz * 256 + sub * 64 + c8 * 8;
            uint32_t so = row * 128 + ((c8 ^ (row & 7)) << 4);
            CP_ASYNC16(smem_u32((pl ? SM_WLO(sub) : SM_WHI(sub)) + so), src);
        }
    }
    CP_COMMIT();

#define LOADH(buf, s, rp) do {                                                      \
        char* dst_ = SM_HBUF(buf);                                                  \
        const __nv_bfloat16* hh_ = g_hh[rp];                                        \
        const __nv_bfloat16* hl_ = g_hl[rp];                                        \
        _Pragma("unroll")                                                           \
        for (int i = 0; i < 4; ++i) {                                               \
            int c_ = tid + i * 512;                                                 \
            int pl_ = c_ >> 10, rm_ = c_ & 1023, row_ = rm_ >> 3, c8_ = rm_ & 7;    \
            const __nv_bfloat16* src_ = (pl_ ? hl_ : hh_) +                         \
                (size_t)row_ * 1024 + kz * 256 + (s) * 64 + c8_ * 8;                \
            uint32_t so_ = pl_ * 16384 + row_ * 128 + ((c8_ ^ (row_ & 7)) << 4);    \
            CP_ASYNC16(smem_u32(dst_ + so_), src_);                                 \
        }                                                                           \
        CP_COMMIT();                                                                \
    } while (0)

#pragma unroll 1
    for (int t = 1; t < T_; ++t) {
        // wait: region kz h-ready (GEMM input) + own region (slot-reuse safety)
        if (tid == 0) {
            unsigned tgt = 32u * (unsigned)(t - 1);
            while (*(volatile unsigned*)&g_hcnt[kz] < tgt) { }
            if (reg_own != kz)
                while (*(volatile unsigned*)&g_hcnt[reg_own] < tgt) { }
            __threadfence();     // acquire
        }
        __syncthreads();

        const int rp = (t - 1) % 3;
        const int wp = t % 3;

        LOADH(0, 0, rp);
        LOADH(1, 1, rp);

        float cacc[2][4][4];
#pragma unroll
        for (int mi = 0; mi < 2; ++mi)
#pragma unroll
            for (int ni = 0; ni < 4; ++ni)
#pragma unroll
                for (int q = 0; q < 4; ++q) cacc[mi][ni][q] = 0.0f;

#pragma unroll 1
        for (int s = 0; s < 4; ++s) {
            if (s < 3) { CP_WAIT1(); } else { CP_WAIT0(); }
            __syncthreads();

            const char* abase  = SM_HBUF(s % 3);
            const char* bhbase = SM_WHI(s);
            const char* blbase = SM_WLO(s);
#pragma unroll
            for (int j = 0; j < 4; ++j) {
                uint32_t aH[2][4], aL[2][4], bH[2][4], bL[2][4];
#pragma unroll
                for (int mi = 0; mi < 2; ++mi) {
                    int row = wm * 32 + mi * 16 + (lane & 15);
                    int ch  = 2 * j + (lane >> 4);
                    uint32_t off = row * 128 + ((ch ^ (row & 7)) << 4);
                    ldsm4(aH[mi], smem_u32(abase + off));
                    ldsm4(aL[mi], smem_u32(abase + 16384 + off));
                }
#pragma unroll
                for (int pi = 0; pi < 2; ++pi) {
                    int row = wn * 32 + pi * 16 + (lane & 7) + ((lane & 16) >> 1);
                    int ch  = 2 * j + ((lane >> 3) & 1);
                    uint32_t off = row * 128 + ((ch ^ (row & 7)) << 4);
                    ldsm4(bH[pi], smem_u32(bhbase + off));
                    ldsm4(bL[pi], smem_u32(blbase + off));
                }
#pragma unroll
                for (int mi = 0; mi < 2; ++mi)
#pragma unroll
                    for (int ni = 0; ni < 4; ++ni) {
                        uint32_t bh0 = bH[ni >> 1][(ni & 1) * 2];
                        uint32_t bh1 = bH[ni >> 1][(ni & 1) * 2 + 1];
                        uint32_t bl0 = bL[ni >> 1][(ni & 1) * 2];
                        uint32_t bl1 = bL[ni >> 1][(ni & 1) * 2 + 1];
                        mma16816(cacc[mi][ni], aH[mi], bh0, bh1);
                        mma16816(cacc[mi][ni], aH[mi], bl0, bl1);
                        mma16816(cacc[mi][ni], aL[mi], bh0, bh1);
                    }
            }
            if (s + 2 < 4) LOADH((s + 2) % 3, s + 2, rp);
        }

        // ---- write z partials ----
        {
            float* cb = g_zh + (size_t)kz * (B_ * N4_) + nt * 128;
#pragma unroll
            for (int mi = 0; mi < 2; ++mi)
#pragma unroll
                for (int ni = 0; ni < 4; ++ni) {
                    int r   = wm * 32 + mi * 16 + (lane >> 2);
                    int col = wn * 32 + ni * 8 + (lane & 3) * 2;
                    *(float2*)(cb + (size_t)r * N4_ + col) =
                        make_float2(cacc[mi][ni][0], cacc[mi][ni][1]);
                    *(float2*)(cb + (size_t)(r + 8) * N4_ + col) =
                        make_float2(cacc[mi][ni][2], cacc[mi][ni][3]);
                }
        }
        __syncthreads();
        if (tid == 0) {
            __threadfence();                       // release partials
            atomicAdd(&g_pcnt[nt], 1u);
            unsigned tgt = 4u * (unsigned)t;
            while (*(volatile unsigned*)&g_pcnt[nt] < tgt) { }
            __threadfence();                       // acquire partners' partials
        }
        __syncthreads();

        // ---- local eltwise: rows kz*32.., this nt's 32 units ----
        float hv0, hv1;
        {
            size_t rowoff = (size_t)gr * N4_ + nt * 128 + uh * 8;
            const float4* px = (const float4*)(g_zx + (size_t)t * B_ * N4_ + rowoff);
            float4 z0 = __ldg(px + 0);
            float4 z1 = __ldg(px + 1);
#pragma unroll
            for (int kzi = 0; kzi < NSPLIT; ++kzi) {
                const float4* pp = (const float4*)(g_zh + (size_t)kzi * (B_ * N4_) + rowoff);
                float4 a0 = __ldcg(pp + 0), a1 = __ldcg(pp + 1);
                z0.x += a0.x; z0.y += a0.y; z0.z += a0.z; z0.w += a0.w;
                z1.x += a1.x; z1.y += a1.y; z1.z += a1.z; z1.w += a1.w;
            }
            float4 bb0 = g_b4[u0];
            float4 bb1 = g_b4[u0 + 1];
            {
                float zg = z0.x + bb0.x, zi = z0.y + bb0.y;
                float zf = z0.z + bb0.z, zo = z0.w + bb0.w;
                float g  = tanhf(zg);
                float ii = 1.0f / (1.0f + expf(-zi));
                float f  = 1.0f / (1.0f + expf(-zf));
                float o  = 1.0f / (1.0f + expf(-zo));
                c0 = f * c0 + ii * g;
                hv0 = o * tanhf(c0);
            }
            {
                float zg = z1.x + bb1.x, zi = z1.y + bb1.y;
                float zf = z1.z + bb1.z, zo = z1.w + bb1.w;
                float g  = tanhf(zg);
                float ii = 1.0f / (1.0f + expf(-zi));
                float f  = 1.0f / (1.0f + expf(-zf));
                float o  = 1.0f / (1.0f + expf(-zo));
                c1 = f * c1 + ii * g;
                hv1 = o * tanhf(c1);
            }

            union { __nv_bfloat16 v[2]; uint32_t u; } hh, hl;
            __nv_bfloat16 h0 = __float2bfloat16(hv0);
            __nv_bfloat16 h1 = __float2bfloat16(hv1);
            hh.v[0] = h0; hh.v[1] = h1;
            hl.v[0] = __float2bfloat16(hv0 - __bfloat162float(h0));
            hl.v[1] = __float2bfloat16(hv1 - __bfloat162float(h1));
            *(uint32_t*)(g_hh[wp] + (size_t)gr * 1024 + u0) = hh.u;
            *(uint32_t*)(g_hl[wp] + (size_t)gr * 1024 + u0) = hl.u;
        }
        __syncthreads();
        if (tid == 0) {
            __threadfence();                       // release h planes
            atomicAdd(&g_hcnt[reg_own], 1u);       // h region ready
        }
        // out store off the critical path (device never reads out)
        *(float2*)(out + ((size_t)t * B_ + gr) * 1024 + u0) = make_float2(hv0, hv1);
    }
#undef LOADH
}

// ---------------- prep kernels ----------------
__global__ void split_plane(const float* __restrict__ src, __nv_bfloat16* __restrict__ hi,
                            __nv_bfloat16* __restrict__ lo, int n) {
    int i = blockIdx.x * blockDim.x + threadIdx.x;
    if (i < n) {
        float v = src[i];
        __nv_bfloat16 h = __float2bfloat16(v);
        hi[i] = h;
        lo[i] = __float2bfloat16(v - __bfloat162float(h));
    }
}

// gate-INTERLEAVED weight split: dest row = 4*unit + gate
__global__ void split_W(const float* __restrict__ Wg, const float* __restrict__ Wi,
                        const float* __restrict__ Wf, const float* __restrict__ Wo) {
    int idx = blockIdx.x * blockDim.x + threadIdx.x;
    if (idx >= 4 * 1024 * 2048) return;
    int gate = idx >> 21;
    int rem  = idx & ((1 << 21) - 1);
    int n    = rem >> 11;
    int k    = rem & 2047;
    const float* W = (gate == 0) ? Wg : (gate == 1) ? Wi : (gate == 2) ? Wf : Wo;
    float v = W[(size_t)n * 2048 + k];
    __nv_bfloat16 h = __float2bfloat16(v);
    __nv_bfloat16 l = __float2bfloat16(v - __bfloat162float(h));
    int gr = 4 * n + gate;
    if (k < 1024) {
        g_wxh[(size_t)gr * 1024 + k] = h;
        g_wxl[(size_t)gr * 1024 + k] = l;
    } else {
        g_whh[(size_t)gr * 1024 + (k - 1024)] = h;
        g_whl[(size_t)gr * 1024 + (k - 1024)] = l;
    }
}

__global__ void init_state(float* __restrict__ out,
                           const float* __restrict__ bg, const float* __restrict__ bi,
                           const float* __restrict__ bf, const float* __restrict__ bo) {
    int i = blockIdx.x * blockDim.x + threadIdx.x;
    if (i < BH_) {
        out[i] = 0.0f;                          // output[0] = h0 = 0
        g_hh[0][i] = __float2bfloat16(0.0f);    // h_0 planes (rp of t=1 is buffer 0)
        g_hl[0][i] = __float2bfloat16(0.0f);
    }
    if (i < H_) g_b4[i] = make_float4(bg[i], bi[i], bf[i], bo[i]);
    if (i < 32) g_pcnt[i] = 0;
    if (i < 4)  g_hcnt[i] = 0;
}

// ---------------- launch ----------------
#define GEMM_SMEM (3 * 65536)

extern "C" void kernel_launch(void* const* d_in, const int* in_sizes, int n_in,
                              void* d_out, int out_size)
{
    const float* embeds = (const float*)d_in[0];
    const float* Wg = (const float*)d_in[1];
    const float* Wi = (const float*)d_in[2];
    const float* Wf = (const float*)d_in[3];
    const float* Wo = (const float*)d_in[4];
    const float* bg = (const float*)d_in[5];
    const float* bi = (const float*)d_in[6];
    const float* bf = (const float*)d_in[7];
    const float* bo = (const float*)d_in[8];
    float* out = (float*)d_out;

    cudaFuncSetAttribute(gemm_mma, cudaFuncAttributeMaxDynamicSharedMemorySize, GEMM_SMEM);
    cudaFuncSetAttribute(lstm_persistent, cudaFuncAttributeMaxDynamicSharedMemorySize, PK_SMEM);

    __nv_bfloat16 *p_eh, *p_el, *p_wxh, *p_wxl;
    float *p_zx;
    cudaGetSymbolAddress((void**)&p_eh,  g_eh);
    cudaGetSymbolAddress((void**)&p_el,  g_el);
    cudaGetSymbolAddress((void**)&p_wxh, g_wxh);
    cudaGetSymbolAddress((void**)&p_wxl, g_wxl);
    cudaGetSymbolAddress((void**)&p_zx,  g_zx);

    // prep
    {
        int n = T_ * B_ * E_;
        split_plane<<<(n + 255) / 256, 256>>>(embeds, p_eh, p_el, n);
    }
    split_W<<<(4 * 1024 * 2048 + 255) / 256, 256>>>(Wg, Wi, Wf, Wo);
    init_state<<<(BH_ + 255) / 256, 256>>>(out, bg, bi, bf, bo);

    // batch: Zx[t] = x_t @ Wx'^T for all t (interleaved cols)
    gemm_mma<<<dim3(32, 256, 1), 256, GEMM_SMEM>>>(p_eh, p_el, 1024, p_wxh, p_wxl,
                                                   p_zx, 0, 1024);

    // recurrence: one persistent kernel, region-flag pipeline
    lstm_persistent<<<PK_CTAS, PK_THREADS, PK_SMEM>>>(out);
}

// round 10
// speedup vs baseline: 1.4345x; 1.0042x over previous
#include <cuda_runtime.h>
#include <cuda_bf16.h>
#include <cstdint>

// ---------------- problem constants ----------------
#define T_    256
#define B_    128
#define E_    1024
#define H_    1024
#define N4_   4096
#define BH_   (B_ * H_)
#define NSPLIT 4

// ---------------- static device scratch ----------------
// weights / z use GATE-INTERLEAVED column order: col' = 4*unit + gate
__device__ float          g_zx[(size_t)T_ * B_ * N4_];   // x-part preactivations (interleaved)
__device__ float          g_zh[NSPLIT * B_ * N4_];       // per-step h-part partials
__device__ float4         g_b4[H_];                      // interleaved bias {bg,bi,bf,bo}[u]
__device__ __nv_bfloat16  g_eh[(size_t)T_ * B_ * E_];    // embeds hi
__device__ __nv_bfloat16  g_el[(size_t)T_ * B_ * E_];    // embeds lo
__device__ __nv_bfloat16  g_wxh[N4_ * 1024];             // Wx hi (interleaved rows, K-major)
__device__ __nv_bfloat16  g_wxl[N4_ * 1024];
__device__ __nv_bfloat16  g_whh[N4_ * 1024];             // Wh hi (interleaved rows)
__device__ __nv_bfloat16  g_whl[N4_ * 1024];
__device__ __nv_bfloat16  g_hh[3][BH_];                  // h triple buffer, hi plane
__device__ __nv_bfloat16  g_hl[3][BH_];                  // h triple buffer, lo plane
__device__ unsigned       g_hcnt[4];                     // per-region h-ready counters (monotonic)
__device__ unsigned       g_pcnt[32];                    // per-nt partial counters (monotonic)

// ---------------- arch-generic PTX helpers ----------------
__device__ __forceinline__ uint32_t smem_u32(const void* p) {
    uint32_t a;
    asm("{ .reg .u64 t; cvta.to.shared.u64 t, %1; cvt.u32.u64 %0, t; }" : "=r"(a) : "l"(p));
    return a;
}
__device__ __forceinline__ void ldsm4(uint32_t r[4], uint32_t saddr) {
    asm volatile("ldmatrix.sync.aligned.m8n8.x4.shared.b16 {%0,%1,%2,%3}, [%4];"
                 : "=r"(r[0]), "=r"(r[1]), "=r"(r[2]), "=r"(r[3]) : "r"(saddr));
}
__device__ __forceinline__ void mma16816(float c[4], const uint32_t a[4],
                                         uint32_t b0, uint32_t b1) {
    asm volatile("mma.sync.aligned.m16n8k16.row.col.f32.bf16.bf16.f32 "
                 "{%0,%1,%2,%3}, {%4,%5,%6,%7}, {%8,%9}, {%0,%1,%2,%3};"
                 : "+f"(c[0]), "+f"(c[1]), "+f"(c[2]), "+f"(c[3])
                 : "r"(a[0]), "r"(a[1]), "r"(a[2]), "r"(a[3]), "r"(b0), "r"(b1));
}
#define CP_ASYNC16(dst, src) \
    asm volatile("cp.async.cg.shared.global [%0], [%1], 16;" :: "r"(dst), "l"(src))
#define CP_COMMIT() asm volatile("cp.async.commit_group;" ::: "memory")
#define CP_WAIT0()  asm volatile("cp.async.wait_group 0;" ::: "memory")
#define CP_WAIT1()  asm volatile("cp.async.wait_group 1;" ::: "memory")

// ---------------- batch 3-plane bf16 GEMM (3-stage pipeline, known-good) ----------------
__global__ __launch_bounds__(256, 1)
void gemm_mma(const __nv_bfloat16* __restrict__ Ah, const __nv_bfloat16* __restrict__ Al,
              int lda,
              const __nv_bfloat16* __restrict__ Bh, const __nv_bfloat16* __restrict__ Bl,
              float* __restrict__ C, size_t csplit_stride, int klen)
{
    extern __shared__ __align__(128) char sm[];

    const int tid  = threadIdx.x;
    const int lane = tid & 31;
    const int wid  = tid >> 5;
    const int wm   = wid & 1;
    const int wn   = wid >> 1;
    const int nt = blockIdx.x, mt = blockIdx.y, kz = blockIdx.z;
    const int kofs = kz * klen;
    const int nstages = klen >> 6;

    const __nv_bfloat16* a_h = Ah + (size_t)mt * 128 * lda + kofs;
    const __nv_bfloat16* a_l = Al + (size_t)mt * 128 * lda + kofs;
    const __nv_bfloat16* b_h = Bh + (size_t)nt * 128 * 1024 + kofs;
    const __nv_bfloat16* b_l = Bl + (size_t)nt * 128 * 1024 + kofs;

    const int lrow = tid >> 3;
    const int lc   = tid & 7;

#define LOAD_STAGE(buf, s) do {                                                    \
        char* dst_ = sm + (buf) * 65536;                                           \
        const __nv_bfloat16* s0_ = a_h + (s) * 64;                                 \
        const __nv_bfloat16* s1_ = a_l + (s) * 64;                                 \
        const __nv_bfloat16* s2_ = b_h + (s) * 64;                                 \
        const __nv_bfloat16* s3_ = b_l + (s) * 64;                                 \
        _Pragma("unroll")                                                          \
        for (int p = 0; p < 4; ++p) {                                              \
            int row = lrow + p * 32;                                               \
            uint32_t so = row * 128 + ((lc ^ (row & 7)) << 4);                     \
            CP_ASYNC16(smem_u32(dst_ + 0     + so), s0_ + (size_t)row * lda + lc * 8); \
            CP_ASYNC16(smem_u32(dst_ + 16384 + so), s1_ + (size_t)row * lda + lc * 8); \
            CP_ASYNC16(smem_u32(dst_ + 32768 + so), s2_ + (size_t)row * 1024 + lc * 8); \
            CP_ASYNC16(smem_u32(dst_ + 49152 + so), s3_ + (size_t)row * 1024 + lc * 8); \
        }                                                                          \
        CP_COMMIT();                                                               \
    } while (0)

    float cacc[4][4][4];
#pragma unroll
    for (int mi = 0; mi < 4; ++mi)
#pragma unroll
        for (int ni = 0; ni < 4; ++ni)
#pragma unroll
            for (int q = 0; q < 4; ++q) cacc[mi][ni][q] = 0.0f;

    LOAD_STAGE(0, 0);
    if (nstages > 1) LOAD_STAGE(1, 1);

#pragma unroll 1
    for (int s = 0; s < nstages; ++s) {
        if (s + 1 < nstages) { CP_WAIT1(); } else { CP_WAIT0(); }
        __syncthreads();

        const char* base = sm + (s % 3) * 65536;
#pragma unroll
        for (int j = 0; j < 4; ++j) {
            uint32_t aH[4][4], aL[4][4], bH[2][4], bL[2][4];
#pragma unroll
            for (int mi = 0; mi < 4; ++mi) {
                int row = wm * 64 + mi * 16 + (lane & 15);
                int ch  = 2 * j + (lane >> 4);
                uint32_t off = row * 128 + ((ch ^ (row & 7)) << 4);
                ldsm4(aH[mi], smem_u32(base + 0     + off));
                ldsm4(aL[mi], smem_u32(base + 16384 + off));
            }
#pragma unroll
            for (int pi = 0; pi < 2; ++pi) {
                int row = wn * 32 + pi * 16 + (lane & 7) + ((lane & 16) >> 1);
                int ch  = 2 * j + ((lane >> 3) & 1);
                uint32_t off = row * 128 + ((ch ^ (row & 7)) << 4);
                ldsm4(bH[pi], smem_u32(base + 32768 + off));
                ldsm4(bL[pi], smem_u32(base + 49152 + off));
            }
#pragma unroll
            for (int mi = 0; mi < 4; ++mi)
#pragma unroll
                for (int ni = 0; ni < 4; ++ni) {
                    uint32_t bh0 = bH[ni >> 1][(ni & 1) * 2];
                    uint32_t bh1 = bH[ni >> 1][(ni & 1) * 2 + 1];
                    uint32_t bl0 = bL[ni >> 1][(ni & 1) * 2];
                    uint32_t bl1 = bL[ni >> 1][(ni & 1) * 2 + 1];
                    mma16816(cacc[mi][ni], aH[mi], bh0, bh1);
                    mma16816(cacc[mi][ni], aH[mi], bl0, bl1);
                    mma16816(cacc[mi][ni], aL[mi], bh0, bh1);
                }
        }
        if (s + 2 < nstages) LOAD_STAGE((s + 2) % 3, s + 2);
    }

    float* cb = C + (size_t)kz * csplit_stride + (size_t)mt * 128 * N4_ + nt * 128;
#pragma unroll
    for (int mi = 0; mi < 4; ++mi)
#pragma unroll
        for (int ni = 0; ni < 4; ++ni) {
            int r   = wm * 64 + mi * 16 + (lane >> 2);
            int col = wn * 32 + ni * 8 + (lane & 3) * 2;
            *(float2*)(cb + (size_t)r * N4_ + col) =
                make_float2(cacc[mi][ni][0], cacc[mi][ni][1]);
            *(float2*)(cb + (size_t)(r + 8) * N4_ + col) =
                make_float2(cacc[mi][ni][2], cacc[mi][ni][3]);
        }
#undef LOAD_STAGE
}

// ---------------- persistent recurrence kernel (region-flag pipeline) ----------------
// 128 CTAs x 512 threads. CTA = (nt 0..31, kz 0..3). Resident Wh slab (128KB),
// streamed h (3-buffer smem), producer/consumer region flags, c in registers.
// Region r covers h units produced by nt' in [8r, 8r+8). Consumer (nt,kz) waits
// region kz (its GEMM input) and region nt>>3 (protects its zh slot + h slot reuse).
#define PK_CTAS   128
#define PK_THREADS 512
#define SM_WHI(s)   (sm + (s) * 16384)
#define SM_WLO(s)   (sm + 65536 + (s) * 16384)
#define SM_HBUF(b)  (sm + 131072 + (b) * 32768)
#define PK_SMEM     (131072 + 3 * 32768)      // 229376

__global__ __launch_bounds__(PK_THREADS, 1)
void lstm_persistent(float* __restrict__ out)
{
    extern __shared__ __align__(128) char sm[];

    const int tid  = threadIdx.x;
    const int lane = tid & 31;
    const int wid  = tid >> 5;
    const int wm   = wid & 3;        // 4 warp-rows of 32 m
    const int wn   = wid >> 2;       // 4 warp-cols of 32 n
    const int cta  = blockIdx.x;
    const int nt   = cta & 31;
    const int kz   = cta >> 5;
    const int reg_own = nt >> 3;     // region this CTA's h output belongs to

    // eltwise ownership: rows kz*32 + b_r, unit-pair uh
    const int b_r = tid >> 4;
    const int uh  = tid & 15;
    const int gr  = kz * 32 + b_r;
    const int u0  = nt * 32 + uh * 2;

    float c0 = 0.0f, c1 = 0.0f;      // resident cell state

    // ---- resident W slab: 4 K64 sub-slabs, hi+lo ----
#pragma unroll
    for (int sub = 0; sub < 4; ++sub) {
#pragma unroll
        for (int i = 0; i < 4; ++i) {
            int c_ = tid + i * 512;
            int pl = c_ >> 10, rm = c_ & 1023, row = rm >> 3, c8 = rm & 7;
            const __nv_bfloat16* src = (pl ? g_whl : g_whh) +
                (size_t)(nt * 128 + row) * 1024 + kz * 256 + sub * 64 + c8 * 8;
            uint32_t so = row * 128 + ((c8 ^ (row & 7)) << 4);
            CP_ASYNC16(smem_u32((pl ? SM_WLO(sub) : SM_WHI(sub)) + so), src);
        }
    }
    CP_COMMIT();

#define LOADH(buf, s, rp) do {                                                      \
        char* dst_ = SM_HBUF(buf);                                                  \
        const __nv_bfloat16* hh_ = g_hh[rp];                                        \
        const __nv_bfloat16* hl_ = g_hl[rp];                                        \
        _Pragma("unroll")                                                           \
        for (int i = 0; i < 4; ++i) {                                               \
            int c_ = tid + i * 512;                                                 \
            int pl_ = c_ >> 10, rm_ = c_ & 1023, row_ = rm_ >> 3, c8_ = rm_ & 7;    \
            const __nv_bfloat16* src_ = (pl_ ? hl_ : hh_) +                         \
                (size_t)row_ * 1024 + kz * 256 + (s) * 64 + c8_ * 8;                \
            uint32_t so_ = pl_ * 16384 + row_ * 128 + ((c8_ ^ (row_ & 7)) << 4);    \
            CP_ASYNC16(smem_u32(dst_ + so_), src_);                                 \
        }                                                                           \
        CP_COMMIT();                                                                \
    } while (0)

#pragma unroll 1
    for (int t = 1; t < T_; ++t) {
        // wait: region kz h-ready (GEMM input) + own region (slot-reuse safety)
        if (tid == 0) {
            unsigned tgt = 32u * (unsigned)(t - 1);
            while (*(volatile unsigned*)&g_hcnt[kz] < tgt) { }
            if (reg_own != kz)
                while (*(volatile unsigned*)&g_hcnt[reg_own] < tgt) { }
            __threadfence();     // acquire
        }
        __syncthreads();

        const int rp = (t - 1) % 3;
        const int wp = t % 3;

        LOADH(0, 0, rp);
        LOADH(1, 1, rp);

        float cacc[2][4][4];
#pragma unroll
        for (int mi = 0; mi < 2; ++mi)
#pragma unroll
            for (int ni = 0; ni < 4; ++ni)
#pragma unroll
                for (int q = 0; q < 4; ++q) cacc[mi][ni][q] = 0.0f;

#pragma unroll 1
        for (int s = 0; s < 4; ++s) {
            if (s < 3) { CP_WAIT1(); } else { CP_WAIT0(); }
            __syncthreads();

            const char* abase  = SM_HBUF(s % 3);
            const char* bhbase = SM_WHI(s);
            const char* blbase = SM_WLO(s);
#pragma unroll
            for (int j = 0; j < 4; ++j) {
                uint32_t aH[2][4], aL[2][4], bH[2][4], bL[2][4];
#pragma unroll
                for (int mi = 0; mi < 2; ++mi) {
                    int row = wm * 32 + mi * 16 + (lane & 15);
                    int ch  = 2 * j + (lane >> 4);
                    uint32_t off = row * 128 + ((ch ^ (row & 7)) << 4);
                    ldsm4(aH[mi], smem_u32(abase + off));
                    ldsm4(aL[mi], smem_u32(abase + 16384 + off));
                }
#pragma unroll
                for (int pi = 0; pi < 2; ++pi) {
                    int row = wn * 32 + pi * 16 + (lane & 7) + ((lane & 16) >> 1);
                    int ch  = 2 * j + ((lane >> 3) & 1);
                    uint32_t off = row * 128 + ((ch ^ (row & 7)) << 4);
                    ldsm4(bH[pi], smem_u32(bhbase + off));
                    ldsm4(bL[pi], smem_u32(blbase + off));
                }
#pragma unroll
                for (int mi = 0; mi < 2; ++mi)
#pragma unroll
                    for (int ni = 0; ni < 4; ++ni) {
                        uint32_t bh0 = bH[ni >> 1][(ni & 1) * 2];
                        uint32_t bh1 = bH[ni >> 1][(ni & 1) * 2 + 1];
                        uint32_t bl0 = bL[ni >> 1][(ni & 1) * 2];
                        uint32_t bl1 = bL[ni >> 1][(ni & 1) * 2 + 1];
                        mma16816(cacc[mi][ni], aH[mi], bh0, bh1);
                        mma16816(cacc[mi][ni], aH[mi], bl0, bl1);
                        mma16816(cacc[mi][ni], aL[mi], bh0, bh1);
                    }
            }
            if (s + 2 < 4) LOADH((s + 2) % 3, s + 2, rp);
        }

        // ---- write z partials ----
        {
            float* cb = g_zh + (size_t)kz * (B_ * N4_) + nt * 128;
#pragma unroll
            for (int mi = 0; mi < 2; ++mi)
#pragma unroll
                for (int ni = 0; ni < 4; ++ni) {
                    int r   = wm * 32 + mi * 16 + (lane >> 2);
                    int col = wn * 32 + ni * 8 + (lane & 3) * 2;
                    *(float2*)(cb + (size_t)r * N4_ + col) =
                        make_float2(cacc[mi][ni][0], cacc[mi][ni][1]);
                    *(float2*)(cb + (size_t)(r + 8) * N4_ + col) =
                        make_float2(cacc[mi][ni][2], cacc[mi][ni][3]);
                }
        }
        __syncthreads();
        if (tid == 0) {
            __threadfence();                       // release partials
            atomicAdd(&g_pcnt[nt], 1u);
            unsigned tgt = 4u * (unsigned)t;
            while (*(volatile unsigned*)&g_pcnt[nt] < tgt) { }
            __threadfence();                       // acquire partners' partials
        }
        __syncthreads();

        // ---- local eltwise: rows kz*32.., this nt's 32 units ----
        float hv0, hv1;
        {
            size_t rowoff = (size_t)gr * N4_ + nt * 128 + uh * 8;
            const float4* px = (const float4*)(g_zx + (size_t)t * B_ * N4_ + rowoff);
            float4 z0 = __ldg(px + 0);
            float4 z1 = __ldg(px + 1);
#pragma unroll
            for (int kzi = 0; kzi < NSPLIT; ++kzi) {
                const float4* pp = (const float4*)(g_zh + (size_t)kzi * (B_ * N4_) + rowoff);
                float4 a0 = __ldcg(pp + 0), a1 = __ldcg(pp + 1);
                z0.x += a0.x; z0.y += a0.y; z0.z += a0.z; z0.w += a0.w;
                z1.x += a1.x; z1.y += a1.y; z1.z += a1.z; z1.w += a1.w;
            }
            float4 bb0 = g_b4[u0];
            float4 bb1 = g_b4[u0 + 1];
            {
                float zg = z0.x + bb0.x, zi = z0.y + bb0.y;
                float zf = z0.z + bb0.z, zo = z0.w + bb0.w;
                float g  = tanhf(zg);
                float ii = 1.0f / (1.0f + expf(-zi));
                float f  = 1.0f / (1.0f + expf(-zf));
                float o  = 1.0f / (1.0f + expf(-zo));
                c0 = f * c0 + ii * g;
                hv0 = o * tanhf(c0);
            }
            {
                float zg = z1.x + bb1.x, zi = z1.y + bb1.y;
                float zf = z1.z + bb1.z, zo = z1.w + bb1.w;
                float g  = tanhf(zg);
                float ii = 1.0f / (1.0f + expf(-zi));
                float f  = 1.0f / (1.0f + expf(-zf));
                float o  = 1.0f / (1.0f + expf(-zo));
                c1 = f * c1 + ii * g;
                hv1 = o * tanhf(c1);
            }

            union { __nv_bfloat16 v[2]; uint32_t u; } hh, hl;
            __nv_bfloat16 h0 = __float2bfloat16(hv0);
            __nv_bfloat16 h1 = __float2bfloat16(hv1);
            hh.v[0] = h0; hh.v[1] = h1;
            hl.v[0] = __float2bfloat16(hv0 - __bfloat162float(h0));
            hl.v[1] = __float2bfloat16(hv1 - __bfloat162float(h1));
            *(uint32_t*)(g_hh[wp] + (size_t)gr * 1024 + u0) = hh.u;
            *(uint32_t*)(g_hl[wp] + (size_t)gr * 1024 + u0) = hl.u;
        }
        __syncthreads();
        if (tid == 0) {
            __threadfence();                       // release h planes
            atomicAdd(&g_hcnt[reg_own], 1u);       // h region ready
        }
        // out store off the critical path (device never reads out)
        *(float2*)(out + ((size_t)t * B_ + gr) * 1024 + u0) = make_float2(hv0, hv1);
    }
#undef LOADH
}

// ---------------- prep kernels ----------------
__global__ void split_plane(const float* __restrict__ src, __nv_bfloat16* __restrict__ hi,
                            __nv_bfloat16* __restrict__ lo, int n) {
    int i = blockIdx.x * blockDim.x + threadIdx.x;
    if (i < n) {
        float v = src[i];
        __nv_bfloat16 h = __float2bfloat16(v);
        hi[i] = h;
        lo[i] = __float2bfloat16(v - __bfloat162float(h));
    }
}

// gate-INTERLEAVED weight split: dest row = 4*unit + gate
__global__ void split_W(const float* __restrict__ Wg, const float* __restrict__ Wi,
                        const float* __restrict__ Wf, const float* __restrict__ Wo) {
    int idx = blockIdx.x * blockDim.x + threadIdx.x;
    if (idx >= 4 * 1024 * 2048) return;
    int gate = idx >> 21;
    int rem  = idx & ((1 << 21) - 1);
    int n    = rem >> 11;
    int k    = rem & 2047;
    const float* W = (gate == 0) ? Wg : (gate == 1) ? Wi : (gate == 2) ? Wf : Wo;
    float v = W[(size_t)n * 2048 + k];
    __nv_bfloat16 h = __float2bfloat16(v);
    __nv_bfloat16 l = __float2bfloat16(v - __bfloat162float(h));
    int gr = 4 * n + gate;
    if (k < 1024) {
        g_wxh[(size_t)gr * 1024 + k] = h;
        g_wxl[(size_t)gr * 1024 + k] = l;
    } else {
        g_whh[(size_t)gr * 1024 + (k - 1024)] = h;
        g_whl[(size_t)gr * 1024 + (k - 1024)] = l;
    }
}

__global__ void init_state(float* __restrict__ out,
                           const float* __restrict__ bg, const float* __restrict__ bi,
                           const float* __restrict__ bf, const float* __restrict__ bo) {
    int i = blockIdx.x * blockDim.x + threadIdx.x;
    if (i < BH_) {
        out[i] = 0.0f;                          // output[0] = h0 = 0
        g_hh[0][i] = __float2bfloat16(0.0f);    // h_0 planes (rp of t=1 is buffer 0)
        g_hl[0][i] = __float2bfloat16(0.0f);
    }
    if (i < H_) g_b4[i] = make_float4(bg[i], bi[i], bf[i], bo[i]);
    if (i < 32) g_pcnt[i] = 0;
    if (i < 4)  g_hcnt[i] = 0;
}

// ---------------- launch ----------------
#define GEMM_SMEM (3 * 65536)

extern "C" void kernel_launch(void* const* d_in, const int* in_sizes, int n_in,
                              void* d_out, int out_size)
{
    const float* embeds = (const float*)d_in[0];
    const float* Wg = (const float*)d_in[1];
    const float* Wi = (const float*)d_in[2];
    const float* Wf = (const float*)d_in[3];
    const float* Wo = (const float*)d_in[4];
    const float* bg = (const float*)d_in[5];
    const float* bi = (const float*)d_in[6];
    const float* bf = (const float*)d_in[7];
    const float* bo = (const float*)d_in[8];
    float* out = (float*)d_out;

    cudaFuncSetAttribute(gemm_mma, cudaFuncAttributeMaxDynamicSharedMemorySize, GEMM_SMEM);
    cudaFuncSetAttribute(lstm_persistent, cudaFuncAttributeMaxDynamicSharedMemorySize, PK_SMEM);

    __nv_bfloat16 *p_eh, *p_el, *p_wxh, *p_wxl;
    float *p_zx;
    cudaGetSymbolAddress((void**)&p_eh,  g_eh);
    cudaGetSymbolAddress((void**)&p_el,  g_el);
    cudaGetSymbolAddress((void**)&p_wxh, g_wxh);
    cudaGetSymbolAddress((void**)&p_wxl, g_wxl);
    cudaGetSymbolAddress((void**)&p_zx,  g_zx);

    // prep
    {
        int n = T_ * B_ * E_;
        split_plane<<<(n + 255) / 256, 256>>>(embeds, p_eh, p_el, n);
    }
    split_W<<<(4 * 1024 * 2048 + 255) / 256, 256>>>(Wg, Wi, Wf, Wo);
    init_state<<<(BH_ + 255) / 256, 256>>>(out, bg, bi, bf, bo);

    // batch: Zx[t] = x_t @ Wx'^T for all t (interleaved cols)
    gemm_mma<<<dim3(32, 256, 1), 256, GEMM_SMEM>>>(p_eh, p_el, 1024, p_wxh, p_wxl,
                                                   p_zx, 0, 1024);

    // recurrence: one persistent kernel, region-flag pipeline
    lstm_persistent<<<PK_CTAS, PK_THREADS, PK_SMEM>>>(out);
}

// round 11
// speedup vs baseline: 1.4363x; 1.0013x over previous
#include <cuda_runtime.h>
#include <cuda_bf16.h>
#include <cstdint>

// ---------------- problem constants ----------------
#define T_    256
#define B_    128
#define E_    1024
#define H_    1024
#define N4_   4096
#define BH_   (B_ * H_)
#define NSPLIT 4

// ---------------- static device scratch ----------------
// weights / z use GATE-INTERLEAVED column order: col' = 4*unit + gate
__device__ float          g_zx[(size_t)T_ * B_ * N4_];   // x-part preactivations (interleaved)
__device__ float          g_zh[NSPLIT * B_ * N4_];       // per-step h-part partials
__device__ float4         g_b4[H_];                      // interleaved bias {bg,bi,bf,bo}[u]
__device__ __nv_bfloat16  g_eh[(size_t)T_ * B_ * E_];    // embeds hi
__device__ __nv_bfloat16  g_el[(size_t)T_ * B_ * E_];    // embeds lo
__device__ __nv_bfloat16  g_wxh[N4_ * 1024];             // Wx hi (interleaved rows, K-major)
__device__ __nv_bfloat16  g_wxl[N4_ * 1024];
__device__ __nv_bfloat16  g_whh[N4_ * 1024];             // Wh hi (interleaved rows)
__device__ __nv_bfloat16  g_whl[N4_ * 1024];
__device__ __nv_bfloat16  g_hh[3][BH_];                  // h triple buffer, hi plane
__device__ __nv_bfloat16  g_hl[3][BH_];                  // h triple buffer, lo plane
__device__ unsigned       g_hcnt[4];                     // per-region h-ready counters (monotonic)
__device__ unsigned       g_pcnt[32];                    // per-nt partial counters (monotonic)

// ---------------- arch-generic PTX helpers ----------------
__device__ __forceinline__ uint32_t smem_u32(const void* p) {
    uint32_t a;
    asm("{ .reg .u64 t; cvta.to.shared.u64 t, %1; cvt.u32.u64 %0, t; }" : "=r"(a) : "l"(p));
    return a;
}
__device__ __forceinline__ void ldsm4(uint32_t r[4], uint32_t saddr) {
    asm volatile("ldmatrix.sync.aligned.m8n8.x4.shared.b16 {%0,%1,%2,%3}, [%4];"
                 : "=r"(r[0]), "=r"(r[1]), "=r"(r[2]), "=r"(r[3]) : "r"(saddr));
}
__device__ __forceinline__ void mma16816(float c[4], const uint32_t a[4],
                                         uint32_t b0, uint32_t b1) {
    asm volatile("mma.sync.aligned.m16n8k16.row.col.f32.bf16.bf16.f32 "
                 "{%0,%1,%2,%3}, {%4,%5,%6,%7}, {%8,%9}, {%0,%1,%2,%3};"
                 : "+f"(c[0]), "+f"(c[1]), "+f"(c[2]), "+f"(c[3])
                 : "r"(a[0]), "r"(a[1]), "r"(a[2]), "r"(a[3]), "r"(b0), "r"(b1));
}
#define CP_ASYNC16(dst, src) \
    asm volatile("cp.async.cg.shared.global [%0], [%1], 16;" :: "r"(dst), "l"(src))
#define CP_COMMIT() asm volatile("cp.async.commit_group;" ::: "memory")
#define CP_WAIT0()  asm volatile("cp.async.wait_group 0;" ::: "memory")
#define CP_WAIT1()  asm volatile("cp.async.wait_group 1;" ::: "memory")

// ---------------- batch 3-plane bf16 GEMM (3-stage pipeline, known-good) ----------------
__global__ __launch_bounds__(256, 1)
void gemm_mma(const __nv_bfloat16* __restrict__ Ah, const __nv_bfloat16* __restrict__ Al,
              int lda,
              const __nv_bfloat16* __restrict__ Bh, const __nv_bfloat16* __restrict__ Bl,
              float* __restrict__ C, size_t csplit_stride, int klen)
{
    extern __shared__ __align__(128) char sm[];

    const int tid  = threadIdx.x;
    const int lane = tid & 31;
    const int wid  = tid >> 5;
    const int wm   = wid & 1;
    const int wn   = wid >> 1;
    const int nt = blockIdx.x, mt = blockIdx.y, kz = blockIdx.z;
    const int kofs = kz * klen;
    const int nstages = klen >> 6;

    const __nv_bfloat16* a_h = Ah + (size_t)mt * 128 * lda + kofs;
    const __nv_bfloat16* a_l = Al + (size_t)mt * 128 * lda + kofs;
    const __nv_bfloat16* b_h = Bh + (size_t)nt * 128 * 1024 + kofs;
    const __nv_bfloat16* b_l = Bl + (size_t)nt * 128 * 1024 + kofs;

    const int lrow = tid >> 3;
    const int lc   = tid & 7;

#define LOAD_STAGE(buf, s) do {                                                    \
        char* dst_ = sm + (buf) * 65536;                                           \
        const __nv_bfloat16* s0_ = a_h + (s) * 64;                                 \
        const __nv_bfloat16* s1_ = a_l + (s) * 64;                                 \
        const __nv_bfloat16* s2_ = b_h + (s) * 64;                                 \
        const __nv_bfloat16* s3_ = b_l + (s) * 64;                                 \
        _Pragma("unroll")                                                          \
        for (int p = 0; p < 4; ++p) {                                              \
            int row = lrow + p * 32;                                               \
            uint32_t so = row * 128 + ((lc ^ (row & 7)) << 4);                     \
            CP_ASYNC16(smem_u32(dst_ + 0     + so), s0_ + (size_t)row * lda + lc * 8); \
            CP_ASYNC16(smem_u32(dst_ + 16384 + so), s1_ + (size_t)row * lda + lc * 8); \
            CP_ASYNC16(smem_u32(dst_ + 32768 + so), s2_ + (size_t)row * 1024 + lc * 8); \
            CP_ASYNC16(smem_u32(dst_ + 49152 + so), s3_ + (size_t)row * 1024 + lc * 8); \
        }                                                                          \
        CP_COMMIT();                                                               \
    } while (0)

    float cacc[4][4][4];
#pragma unroll
    for (int mi = 0; mi < 4; ++mi)
#pragma unroll
        for (int ni = 0; ni < 4; ++ni)
#pragma unroll
            for (int q = 0; q < 4; ++q) cacc[mi][ni][q] = 0.0f;

    LOAD_STAGE(0, 0);
    if (nstages > 1) LOAD_STAGE(1, 1);

#pragma unroll 1
    for (int s = 0; s < nstages; ++s) {
        if (s + 1 < nstages) { CP_WAIT1(); } else { CP_WAIT0(); }
        __syncthreads();

        const char* base = sm + (s % 3) * 65536;
#pragma unroll
        for (int j = 0; j < 4; ++j) {
            uint32_t aH[4][4], aL[4][4], bH[2][4], bL[2][4];
#pragma unroll
            for (int mi = 0; mi < 4; ++mi) {
                int row = wm * 64 + mi * 16 + (lane & 15);
                int ch  = 2 * j + (lane >> 4);
                uint32_t off = row * 128 + ((ch ^ (row & 7)) << 4);
                ldsm4(aH[mi], smem_u32(base + 0     + off));
                ldsm4(aL[mi], smem_u32(base + 16384 + off));
            }
#pragma unroll
            for (int pi = 0; pi < 2; ++pi) {
                int row = wn * 32 + pi * 16 + (lane & 7) + ((lane & 16) >> 1);
                int ch  = 2 * j + ((lane >> 3) & 1);
                uint32_t off = row * 128 + ((ch ^ (row & 7)) << 4);
                ldsm4(bH[pi], smem_u32(base + 32768 + off));
                ldsm4(bL[pi], smem_u32(base + 49152 + off));
            }
#pragma unroll
            for (int mi = 0; mi < 4; ++mi)
#pragma unroll
                for (int ni = 0; ni < 4; ++ni) {
                    uint32_t bh0 = bH[ni >> 1][(ni & 1) * 2];
                    uint32_t bh1 = bH[ni >> 1][(ni & 1) * 2 + 1];
                    uint32_t bl0 = bL[ni >> 1][(ni & 1) * 2];
                    uint32_t bl1 = bL[ni >> 1][(ni & 1) * 2 + 1];
                    mma16816(cacc[mi][ni], aH[mi], bh0, bh1);
                    mma16816(cacc[mi][ni], aH[mi], bl0, bl1);
                    mma16816(cacc[mi][ni], aL[mi], bh0, bh1);
                }
        }
        if (s + 2 < nstages) LOAD_STAGE((s + 2) % 3, s + 2);
    }

    float* cb = C + (size_t)kz * csplit_stride + (size_t)mt * 128 * N4_ + nt * 128;
#pragma unroll
    for (int mi = 0; mi < 4; ++mi)
#pragma unroll
        for (int ni = 0; ni < 4; ++ni) {
            int r   = wm * 64 + mi * 16 + (lane >> 2);
            int col = wn * 32 + ni * 8 + (lane & 3) * 2;
            *(float2*)(cb + (size_t)r * N4_ + col) =
                make_float2(cacc[mi][ni][0], cacc[mi][ni][1]);
            *(float2*)(cb + (size_t)(r + 8) * N4_ + col) =
                make_float2(cacc[mi][ni][2], cacc[mi][ni][3]);
        }
#undef LOAD_STAGE
}

// ---------------- persistent recurrence kernel (region-flag pipeline) ----------------
// 128 CTAs x 512 threads. CTA = (nt 0..31, kz 0..3). Resident Wh slab (128KB),
// streamed h (3-buffer smem), producer/consumer region flags, c in registers.
// Region r covers h units produced by nt' in [8r, 8r+8). Consumer (nt,kz) waits
// region kz (its GEMM input) and region nt>>3 (protects its zh slot + h slot reuse).
#define PK_CTAS   128
#define PK_THREADS 512
#define SM_WHI(s)   (sm + (s) * 16384)
#define SM_WLO(s)   (sm + 65536 + (s) * 16384)
#define SM_HBUF(b)  (sm + 131072 + (b) * 32768)
#define PK_SMEM     (131072 + 3 * 32768)      // 229376

__global__ __launch_bounds__(PK_THREADS, 1)
void lstm_persistent(float* __restrict__ out)
{
    extern __shared__ __align__(128) char sm[];

    const int tid  = threadIdx.x;
    const int lane = tid & 31;
    const int wid  = tid >> 5;
    const int wm   = wid & 3;        // 4 warp-rows of 32 m
    const int wn   = wid >> 2;       // 4 warp-cols of 32 n
    const int cta  = blockIdx.x;
    const int nt   = cta & 31;
    const int kz   = cta >> 5;
    const int reg_own = nt >> 3;     // region this CTA's h output belongs to

    // eltwise ownership: rows kz*32 + b_r, unit-pair uh
    const int b_r = tid >> 4;
    const int uh  = tid & 15;
    const int gr  = kz * 32 + b_r;
    const int u0  = nt * 32 + uh * 2;

    float c0 = 0.0f, c1 = 0.0f;      // resident cell state

    // ---- resident W slab: 4 K64 sub-slabs, hi+lo ----
#pragma unroll
    for (int sub = 0; sub < 4; ++sub) {
#pragma unroll
        for (int i = 0; i < 4; ++i) {
            int c_ = tid + i * 512;
            int pl = c_ >> 10, rm = c_ & 1023, row = rm >> 3, c8 = rm & 7;
            const __nv_bfloat16* src = (pl ? g_whl : g_whh) +
                (size_t)(nt * 128 + row) * 1024 + kz * 256 + sub * 64 + c8 * 8;
            uint32_t so = row * 128 + ((c8 ^ (row & 7)) << 4);
            CP_ASYNC16(smem_u32((pl ? SM_WLO(sub) : SM_WHI(sub)) + so), src);
        }
    }
    CP_COMMIT();

#define LOADH(buf, s, rp) do {                                                      \
        char* dst_ = SM_HBUF(buf);                                                  \
        const __nv_bfloat16* hh_ = g_hh[rp];                                        \
        const __nv_bfloat16* hl_ = g_hl[rp];                                        \
        _Pragma("unroll")                                                           \
        for (int i = 0; i < 4; ++i) {                                               \
            int c_ = tid + i * 512;                                                 \
            int pl_ = c_ >> 10, rm_ = c_ & 1023, row_ = rm_ >> 3, c8_ = rm_ & 7;    \
            const __nv_bfloat16* src_ = (pl_ ? hl_ : hh_) +                         \
                (size_t)row_ * 1024 + kz * 256 + (s) * 64 + c8_ * 8;                \
            uint32_t so_ = pl_ * 16384 + row_ * 128 + ((c8_ ^ (row_ & 7)) << 4);    \
            CP_ASYNC16(smem_u32(dst_ + so_), src_);                                 \
        }                                                                           \
        CP_COMMIT();                                                                \
    } while (0)

#pragma unroll 1
    for (int t = 1; t < T_; ++t) {
        // wait: region kz h-ready (GEMM input) + own region (slot-reuse safety)
        if (tid == 0) {
            unsigned tgt = 32u * (unsigned)(t - 1);
            while (*(volatile unsigned*)&g_hcnt[kz] < tgt) { }
            if (reg_own != kz)
                while (*(volatile unsigned*)&g_hcnt[reg_own] < tgt) { }
            __threadfence();     // acquire
        }
        __syncthreads();

        const int rp = (t - 1) % 3;
        const int wp = t % 3;

        LOADH(0, 0, rp);
        LOADH(1, 1, rp);

        float cacc[2][4][4];
#pragma unroll
        for (int mi = 0; mi < 2; ++mi)
#pragma unroll
            for (int ni = 0; ni < 4; ++ni)
#pragma unroll
                for (int q = 0; q < 4; ++q) cacc[mi][ni][q] = 0.0f;

#pragma unroll 1
        for (int s = 0; s < 4; ++s) {
            if (s < 3) { CP_WAIT1(); } else { CP_WAIT0(); }
            __syncthreads();

            const char* abase  = SM_HBUF(s % 3);
            const char* bhbase = SM_WHI(s);
            const char* blbase = SM_WLO(s);
#pragma unroll
            for (int j = 0; j < 4; ++j) {
                uint32_t aH[2][4], aL[2][4], bH[2][4], bL[2][4];
#pragma unroll
                for (int mi = 0; mi < 2; ++mi) {
                    int row = wm * 32 + mi * 16 + (lane & 15);
                    int ch  = 2 * j + (lane >> 4);
                    uint32_t off = row * 128 + ((ch ^ (row & 7)) << 4);
                    ldsm4(aH[mi], smem_u32(abase + off));
                    ldsm4(aL[mi], smem_u32(abase + 16384 + off));
                }
#pragma unroll
                for (int pi = 0; pi < 2; ++pi) {
                    int row = wn * 32 + pi * 16 + (lane & 7) + ((lane & 16) >> 1);
                    int ch  = 2 * j + ((lane >> 3) & 1);
                    uint32_t off = row * 128 + ((ch ^ (row & 7)) << 4);
                    ldsm4(bH[pi], smem_u32(bhbase + off));
                    ldsm4(bL[pi], smem_u32(blbase + off));
                }
#pragma unroll
                for (int mi = 0; mi < 2; ++mi)
#pragma unroll
                    for (int ni = 0; ni < 4; ++ni) {
                        uint32_t bh0 = bH[ni >> 1][(ni & 1) * 2];
                        uint32_t bh1 = bH[ni >> 1][(ni & 1) * 2 + 1];
                        uint32_t bl0 = bL[ni >> 1][(ni & 1) * 2];
                        uint32_t bl1 = bL[ni >> 1][(ni & 1) * 2 + 1];
                        mma16816(cacc[mi][ni], aH[mi], bh0, bh1);
                        mma16816(cacc[mi][ni], aH[mi], bl0, bl1);
                        mma16816(cacc[mi][ni], aL[mi], bh0, bh1);
                    }
            }
            if (s + 2 < 4) LOADH((s + 2) % 3, s + 2, rp);
        }

        // ---- write z partials ----
        {
            float* cb = g_zh + (size_t)kz * (B_ * N4_) + nt * 128;
#pragma unroll
            for (int mi = 0; mi < 2; ++mi)
#pragma unroll
                for (int ni = 0; ni < 4; ++ni) {
                    int r   = wm * 32 + mi * 16 + (lane >> 2);
                    int col = wn * 32 + ni * 8 + (lane & 3) * 2;
                    *(float2*)(cb + (size_t)r * N4_ + col) =
                        make_float2(cacc[mi][ni][0], cacc[mi][ni][1]);
                    *(float2*)(cb + (size_t)(r + 8) * N4_ + col) =
                        make_float2(cacc[mi][ni][2], cacc[mi][ni][3]);
                }
        }
        __syncthreads();
        if (tid == 0) {
            __threadfence();                       // release partials
            atomicAdd(&g_pcnt[nt], 1u);
            unsigned tgt = 4u * (unsigned)t;
            while (*(volatile unsigned*)&g_pcnt[nt] < tgt) { }
            __threadfence();                       // acquire partners' partials
        }
        __syncthreads();

        // ---- local eltwise: rows kz*32.., this nt's 32 units ----
        float hv0, hv1;
        {
            size_t rowoff = (size_t)gr * N4_ + nt * 128 + uh * 8;
            const float4* px = (const float4*)(g_zx + (size_t)t * B_ * N4_ + rowoff);
            float4 z0 = __ldg(px + 0);
            float4 z1 = __ldg(px + 1);
#pragma unroll
            for (int kzi = 0; kzi < NSPLIT; ++kzi) {
                const float4* pp = (const float4*)(g_zh + (size_t)kzi * (B_ * N4_) + rowoff);
                float4 a0 = __ldcg(pp + 0), a1 = __ldcg(pp + 1);
                z0.x += a0.x; z0.y += a0.y; z0.z += a0.z; z0.w += a0.w;
                z1.x += a1.x; z1.y += a1.y; z1.z += a1.z; z1.w += a1.w;
            }
            float4 bb0 = g_b4[u0];
            float4 bb1 = g_b4[u0 + 1];
            {
                float zg = z0.x + bb0.x, zi = z0.y + bb0.y;
                float zf = z0.z + bb0.z, zo = z0.w + bb0.w;
                float g  = tanhf(zg);
                float ii = 1.0f / (1.0f + expf(-zi));
                float f  = 1.0f / (1.0f + expf(-zf));
                float o  = 1.0f / (1.0f + expf(-zo));
                c0 = f * c0 + ii * g;
                hv0 = o * tanhf(c0);
            }
            {
                float zg = z1.x + bb1.x, zi = z1.y + bb1.y;
                float zf = z1.z + bb1.z, zo = z1.w + bb1.w;
                float g  = tanhf(zg);
                float ii = 1.0f / (1.0f + expf(-zi));
                float f  = 1.0f / (1.0f + expf(-zf));
                float o  = 1.0f / (1.0f + expf(-zo));
                c1 = f * c1 + ii * g;
                hv1 = o * tanhf(c1);
            }

            union { __nv_bfloat16 v[2]; uint32_t u; } hh, hl;
            __nv_bfloat16 h0 = __float2bfloat16(hv0);
            __nv_bfloat16 h1 = __float2bfloat16(hv1);
            hh.v[0] = h0; hh.v[1] = h1;
            hl.v[0] = __float2bfloat16(hv0 - __bfloat162float(h0));
            hl.v[1] = __float2bfloat16(hv1 - __bfloat162float(h1));
            *(uint32_t*)(g_hh[wp] + (size_t)gr * 1024 + u0) = hh.u;
            *(uint32_t*)(g_hl[wp] + (size_t)gr * 1024 + u0) = hl.u;
        }
        __syncthreads();
        if (tid == 0) {
            __threadfence();                       // release h planes
            atomicAdd(&g_hcnt[reg_own], 1u);       // h region ready
        }
        // out store off the critical path (device never reads out)
        *(float2*)(out + ((size_t)t * B_ + gr) * 1024 + u0) = make_float2(hv0, hv1);
    }
#undef LOADH
}

// ---------------- prep kernels ----------------
__global__ void split_plane(const float* __restrict__ src, __nv_bfloat16* __restrict__ hi,
                            __nv_bfloat16* __restrict__ lo, int n) {
    int i = blockIdx.x * blockDim.x + threadIdx.x;
    if (i < n) {
        float v = src[i];
        __nv_bfloat16 h = __float2bfloat16(v);
        hi[i] = h;
        lo[i] = __float2bfloat16(v - __bfloat162float(h));
    }
}

// gate-INTERLEAVED weight split: dest row = 4*unit + gate
__global__ void split_W(const float* __restrict__ Wg, const float* __restrict__ Wi,
                        const float* __restrict__ Wf, const float* __restrict__ Wo) {
    int idx = blockIdx.x * blockDim.x + threadIdx.x;
    if (idx >= 4 * 1024 * 2048) return;
    int gate = idx >> 21;
    int rem  = idx & ((1 << 21) - 1);
    int n    = rem >> 11;
    int k    = rem & 2047;
    const float* W = (gate == 0) ? Wg : (gate == 1) ? Wi : (gate == 2) ? Wf : Wo;
    float v = W[(size_t)n * 2048 + k];
    __nv_bfloat16 h = __float2bfloat16(v);
    __nv_bfloat16 l = __float2bfloat16(v - __bfloat162float(h));
    int gr = 4 * n + gate;
    if (k < 1024) {
        g_wxh[(size_t)gr * 1024 + k] = h;
        g_wxl[(size_t)gr * 1024 + k] = l;
    } else {
        g_whh[(size_t)gr * 1024 + (k - 1024)] = h;
        g_whl[(size_t)gr * 1024 + (k - 1024)] = l;
    }
}

__global__ void init_state(float* __restrict__ out,
                           const float* __restrict__ bg, const float* __restrict__ bi,
                           const float* __restrict__ bf, const float* __restrict__ bo) {
    int i = blockIdx.x * blockDim.x + threadIdx.x;
    if (i < BH_) {
        out[i] = 0.0f;                          // output[0] = h0 = 0
        g_hh[0][i] = __float2bfloat16(0.0f);    // h_0 planes (rp of t=1 is buffer 0)
        g_hl[0][i] = __float2bfloat16(0.0f);
    }
    if (i < H_) g_b4[i] = make_float4(bg[i], bi[i], bf[i], bo[i]);
    if (i < 32) g_pcnt[i] = 0;
    if (i < 4)  g_hcnt[i] = 0;
}

// ---------------- launch ----------------
#define GEMM_SMEM (3 * 65536)

extern "C" void kernel_launch(void* const* d_in, const int* in_sizes, int n_in,
                              void* d_out, int out_size)
{
    const float* embeds = (const float*)d_in[0];
    const float* Wg = (const float*)d_in[1];
    const float* Wi = (const float*)d_in[2];
    const float* Wf = (const float*)d_in[3];
    const float* Wo = (const float*)d_in[4];
    const float* bg = (const float*)d_in[5];
    const float* bi = (const float*)d_in[6];
    const float* bf = (const float*)d_in[7];
    const float* bo = (const float*)d_in[8];
    float* out = (float*)d_out;

    cudaFuncSetAttribute(gemm_mma, cudaFuncAttributeMaxDynamicSharedMemorySize, GEMM_SMEM);
    cudaFuncSetAttribute(lstm_persistent, cudaFuncAttributeMaxDynamicSharedMemorySize, PK_SMEM);

    __nv_bfloat16 *p_eh, *p_el, *p_wxh, *p_wxl;
    float *p_zx;
    cudaGetSymbolAddress((void**)&p_eh,  g_eh);
    cudaGetSymbolAddress((void**)&p_el,  g_el);
    cudaGetSymbolAddress((void**)&p_wxh, g_wxh);
    cudaGetSymbolAddress((void**)&p_wxl, g_wxl);
    cudaGetSymbolAddress((void**)&p_zx,  g_zx);

    // prep
    {
        int n = T_ * B_ * E_;
        split_plane<<<(n + 255) / 256, 256>>>(embeds, p_eh, p_el, n);
    }
    split_W<<<(4 * 1024 * 2048 + 255) / 256, 256>>>(Wg, Wi, Wf, Wo);
    init_state<<<(BH_ + 255) / 256, 256>>>(out, bg, bi, bf, bo);

    // batch: Zx[t] = x_t @ Wx'^T for all t (interleaved cols)
    gemm_mma<<<dim3(32, 256, 1), 256, GEMM_SMEM>>>(p_eh, p_el, 1024, p_wxh, p_wxl,
                                                   p_zx, 0, 1024);

    // recurrence: one persistent kernel, region-flag pipeline
    lstm_persistent<<<PK_CTAS, PK_THREADS, PK_SMEM>>>(out);
}